// round 12
// baseline (speedup 1.0000x reference)
#include <cuda_runtime.h>
#include <cstdint>

#define NNODES 50000
#define DFEAT 128

// ---- scratch (device globals: no allocation allowed) ----
__device__ __align__(256) float  g_H[NNODES * DFEAT];   // h = (1+eps)*x + agg
__device__ __align__(256) float  g_Z1[NNODES * DFEAT];  // pre-BN output of linear1
__device__ __align__(256) double g_stats[512];          // sum1,sq1,sum2,sq2 (128 each)
__device__ int g_is64;                                  // edge_index dtype flag

__device__ __forceinline__ uint32_t to_tf32(float x) {
    uint32_t r;
    asm("cvt.rna.tf32.f32 %0, %1;" : "=r"(r) : "f"(x));
    return r;
}

// ============================ small kernels ============================

// zero stats + probe edge dtype. One block, 512 threads.
__global__ void prep_kernel(const void* eiv, int E, int N) {
    int t = threadIdx.x;
    g_stats[t] = 0.0;
    __shared__ int bad;
    if (t == 0) bad = 0;
    __syncthreads();
    const long long* p = (const long long*)eiv;
    int n = E < 1024 ? E : 1024;
    for (int i = t; i < n; i += blockDim.x) {
        long long v = p[i];
        if (v < 0 || v >= (long long)N) atomicOr(&bad, 1);
    }
    __syncthreads();
    if (t == 0) g_is64 = bad ? 0 : 1;
}

// h = (1+eps) * x
__global__ void init_h_kernel(const float* __restrict__ x, const float* __restrict__ eps, int n4) {
    int idx = blockIdx.x * blockDim.x + threadIdx.x;
    if (idx >= n4) return;
    float c = 1.0f + *eps;
    float4 v = ((const float4*)x)[idx];
    v.x *= c; v.y *= c; v.z *= c; v.w *= c;
    ((float4*)g_H)[idx] = v;
}

// edge scatter-add: 8 edges per warp (MLP=8), vector L2 reductions
__global__ void __launch_bounds__(256) scatter_kernel(const float* __restrict__ x,
                                                      const void* __restrict__ eiv, int E) {
    int lane = threadIdx.x & 31;
    int warp = (blockIdx.x * blockDim.x + threadIdx.x) >> 5;
    int e0 = warp * 8;
    if (e0 >= E) return;
    int is64 = g_is64;

    if (e0 + 8 <= E) {
        long long s[8], d[8];
        if (is64) {
            const long long* ei = (const long long*)eiv;
#pragma unroll
            for (int k = 0; k < 8; k++) { s[k] = __ldg(&ei[e0 + k]); d[k] = __ldg(&ei[E + e0 + k]); }
        } else {
            const int* ei = (const int*)eiv;
#pragma unroll
            for (int k = 0; k < 8; k++) { s[k] = __ldg(&ei[e0 + k]); d[k] = __ldg(&ei[E + e0 + k]); }
        }
        float4 v[8];
#pragma unroll
        for (int k = 0; k < 8; k++)
            v[k] = __ldg(((const float4*)(x + s[k] * 128)) + lane);
#pragma unroll
        for (int k = 0; k < 8; k++) {
            float* dp = g_H + d[k] * 128 + (lane << 2);
            asm volatile("red.global.add.v4.f32 [%0], {%1,%2,%3,%4};"
                         :: "l"(dp), "f"(v[k].x), "f"(v[k].y), "f"(v[k].z), "f"(v[k].w) : "memory");
        }
    } else {
        for (int e = e0; e < E; e++) {
            long long s, d;
            if (is64) {
                const long long* ei = (const long long*)eiv;
                s = __ldg(&ei[e]); d = __ldg(&ei[E + e]);
            } else {
                const int* ei = (const int*)eiv;
                s = __ldg(&ei[e]); d = __ldg(&ei[E + e]);
            }
            float4 v = __ldg(((const float4*)(x + s * 128)) + lane);
            float* dp = g_H + d * 128 + (lane << 2);
            asm volatile("red.global.add.v4.f32 [%0], {%1,%2,%3,%4};"
                         :: "l"(dp), "f"(v.x), "f"(v.y), "f"(v.z), "f"(v.w) : "memory");
        }
    }
}

// ============================ tf32 mma.sync GEMM ============================
// Z[m][n] = bias[n] + sum_k f(A[m][k]) * W[n][k]
// MODE 0: A=g_H,  f=identity,                          Z=g_Z1
// MODE 1: A=g_Z1, f=relu(bn1(.)), bn1 finalized inline, Z=Zout
// Block: 128x128 tile, K=128 in smem (stride 132, conflict-free frags).
// 1024 threads = 32 warps in 8(m) x 4(n); warp tile 16x32; mma.m16n8k8.tf32.
// 8 warps/SMSP (vs 4) for latency hiding at identical smem traffic.
// Register double-buffered fragments; column sum/sumsq fused in epilogue.
#define MMA_SMEM_FLOATS (640 + 2 * 128 * 132)
#define MMA_SMEM_BYTES  (MMA_SMEM_FLOATS * 4)

__device__ __forceinline__ void mma_tf32_16n8k8(float c[4], const uint32_t a[4],
                                                uint32_t b0, uint32_t b1) {
    asm volatile(
        "mma.sync.aligned.m16n8k8.row.col.f32.tf32.tf32.f32 "
        "{%0,%1,%2,%3}, {%4,%5,%6,%7}, {%8,%9}, {%0,%1,%2,%3};"
        : "+f"(c[0]), "+f"(c[1]), "+f"(c[2]), "+f"(c[3])
        : "r"(a[0]), "r"(a[1]), "r"(a[2]), "r"(a[3]), "r"(b0), "r"(b1));
}

template <int MODE>
__global__ void __launch_bounds__(1024) mma_gemm(const float* __restrict__ Wmat,
                                                 const float* __restrict__ bias,
                                                 const float* __restrict__ gamma,
                                                 const float* __restrict__ beta,
                                                 float* __restrict__ Zout,
                                                 double invM, int M) {
    extern __shared__ float sm[];
    float* s_bias  = sm;
    float* s_scale = sm + 128;
    float* s_shift = sm + 256;
    float* s_sum   = sm + 384;
    float* s_sq    = sm + 512;
    float* As      = sm + 640;             // [128][132] (tf32 bits)
    float* Bs      = As + 128 * 132;       // [128][132] (tf32 bits), [n][k]
    const uint32_t* As32 = (const uint32_t*)As;
    const uint32_t* Bs32 = (const uint32_t*)Bs;

    const float* A = MODE ? g_Z1 : g_H;
    float* Z       = MODE ? Zout : g_Z1;

    int tid = threadIdx.x;
    int m0 = blockIdx.x * 128;

    if (tid < 128) {
        s_bias[tid] = bias[tid];
        s_sum[tid] = 0.f;
        s_sq[tid]  = 0.f;
        if (MODE) {
            // inline BN1 finalize from g_stats (mul-only, invM precomputed on host)
            double mean = g_stats[tid] * invM;
            double var  = g_stats[128 + tid] * invM - mean * mean;
            float sc = gamma[tid] * rsqrtf((float)var + 1e-5f);
            s_scale[tid] = sc;
            s_shift[tid] = beta[tid] - (float)mean * sc;
        }
    }
    __syncthreads();

    // load B (=W, [n][k] natural layout), tf32-rounded (4096 float4)
#pragma unroll
    for (int i = 0; i < 4; i++) {
        int idx = i * 1024 + tid;
        int n = idx >> 5, k4 = idx & 31;
        float4 v = __ldg(((const float4*)Wmat) + idx);
        uint32_t* dst = (uint32_t*)(Bs + n * 132 + k4 * 4);
        dst[0] = to_tf32(v.x); dst[1] = to_tf32(v.y);
        dst[2] = to_tf32(v.z); dst[3] = to_tf32(v.w);
    }
    // load A tile (fused bn1+relu in MODE 1), tf32-rounded
#pragma unroll
    for (int i = 0; i < 4; i++) {
        int idx = i * 1024 + tid;
        int m = idx >> 5, k4 = idx & 31;
        int gm = m0 + m;
        float4 v = make_float4(0.f, 0.f, 0.f, 0.f);
        if (gm < M) v = __ldg(((const float4*)A) + (size_t)gm * 32 + k4);
        if (MODE) {
            int k = k4 * 4;
            v.x = fmaxf(fmaf(v.x, s_scale[k + 0], s_shift[k + 0]), 0.f);
            v.y = fmaxf(fmaf(v.y, s_scale[k + 1], s_shift[k + 1]), 0.f);
            v.z = fmaxf(fmaf(v.z, s_scale[k + 2], s_shift[k + 2]), 0.f);
            v.w = fmaxf(fmaf(v.w, s_scale[k + 3], s_shift[k + 3]), 0.f);
        }
        uint32_t* dst = (uint32_t*)(As + m * 132 + k4 * 4);
        dst[0] = to_tf32(v.x); dst[1] = to_tf32(v.y);
        dst[2] = to_tf32(v.z); dst[3] = to_tf32(v.w);
    }
    __syncthreads();

    int lane = tid & 31;
    int wid  = tid >> 5;                   // 0..31
    int g = lane >> 2, t = lane & 3;
    int wm = wid >> 2;                     // 0..7 -> 16-row strip
    int wn = wid & 3;                      // 0..3 -> 32-col strip
    int arow = wm * 16;
    int bcol = wn * 32;

    float acc[4][4];
#pragma unroll
    for (int nt = 0; nt < 4; nt++)
#pragma unroll
        for (int q = 0; q < 4; q++) acc[nt][q] = 0.f;

    // double-buffered fragments
    uint32_t a[2][4];
    uint32_t b[2][4][2];

#define LOAD_FRAG(ks, buf)                                                   \
    do {                                                                     \
        int _k0 = (ks) * 8;                                                  \
        a[buf][0] = As32[(arow + g) * 132 + _k0 + t];                        \
        a[buf][1] = As32[(arow + g + 8) * 132 + _k0 + t];                    \
        a[buf][2] = As32[(arow + g) * 132 + _k0 + t + 4];                    \
        a[buf][3] = As32[(arow + g + 8) * 132 + _k0 + t + 4];                \
        _Pragma("unroll")                                                    \
        for (int nt = 0; nt < 4; nt++) {                                     \
            b[buf][nt][0] = Bs32[(bcol + nt * 8 + g) * 132 + _k0 + t];       \
            b[buf][nt][1] = Bs32[(bcol + nt * 8 + g) * 132 + _k0 + t + 4];   \
        }                                                                    \
    } while (0)

    LOAD_FRAG(0, 0);
#pragma unroll
    for (int ks = 0; ks < 16; ks++) {
        int cur = ks & 1;
        if (ks < 15) LOAD_FRAG(ks + 1, cur ^ 1);
#pragma unroll
        for (int nt = 0; nt < 4; nt++)
            mma_tf32_16n8k8(acc[nt], a[cur], b[cur][nt][0], b[cur][nt][1]);
    }
#undef LOAD_FRAG

    // epilogue: bias add, store float2 pairs, fused column stats
#pragma unroll
    for (int nt = 0; nt < 4; nt++) {
        int col = bcol + nt * 8 + 2 * t;
        float bi0 = s_bias[col], bi1 = s_bias[col + 1];
        float cs0 = 0.f, cq0 = 0.f, cs1 = 0.f, cq1 = 0.f;
#pragma unroll
        for (int rr = 0; rr < 2; rr++) {
            int gm = m0 + arow + g + rr * 8;
            if (gm < M) {
                float o0 = acc[nt][rr * 2 + 0] + bi0;
                float o1 = acc[nt][rr * 2 + 1] + bi1;
                *(float2*)(Z + (size_t)gm * 128 + col) = make_float2(o0, o1);
                cs0 += o0; cq0 += o0 * o0;
                cs1 += o1; cq1 += o1 * o1;
            }
        }
        atomicAdd(&s_sum[col], cs0);     atomicAdd(&s_sq[col], cq0);
        atomicAdd(&s_sum[col + 1], cs1); atomicAdd(&s_sq[col + 1], cq1);
    }
    __syncthreads();
    if (tid < 128) {
        double* sum = g_stats + (MODE ? 256 : 0);
        double* sq  = g_stats + (MODE ? 384 : 128);
        atomicAdd(&sum[tid], (double)s_sum[tid]);
        atomicAdd(&sq[tid],  (double)s_sq[tid]);
    }
}

// ---- final: out = relu(bn2(out)) in place; BN2 finalize inlined (mul-only),
//      grid-stride so only ~888 blocks recompute it ----
__global__ void bn_relu_out_kernel(float* __restrict__ out,
                                   const float* __restrict__ gamma,
                                   const float* __restrict__ beta,
                                   double invM, int n4) {
    __shared__ float sc[128], sh[128];
    int t = threadIdx.x;
    if (t < 128) {
        double mean = g_stats[256 + t] * invM;
        double var  = g_stats[384 + t] * invM - mean * mean;
        float s = gamma[t] * rsqrtf((float)var + 1e-5f);
        sc[t] = s;
        sh[t] = beta[t] - (float)mean * s;
    }
    __syncthreads();
    for (int idx = blockIdx.x * blockDim.x + t; idx < n4; idx += gridDim.x * blockDim.x) {
        float4 v = ((float4*)out)[idx];
        int k = (idx & 31) * 4;
        v.x = fmaxf(fmaf(v.x, sc[k + 0], sh[k + 0]), 0.f);
        v.y = fmaxf(fmaf(v.y, sc[k + 1], sh[k + 1]), 0.f);
        v.z = fmaxf(fmaf(v.z, sc[k + 2], sh[k + 2]), 0.f);
        v.w = fmaxf(fmaf(v.w, sc[k + 3], sh[k + 3]), 0.f);
        ((float4*)out)[idx] = v;
    }
}

extern "C" void kernel_launch(void* const* d_in, const int* in_sizes, int n_in,
                              void* d_out, int out_size) {
    const float* x   = (const float*)d_in[0];
    const void*  ei  = d_in[1];
    // d_in[2] = batch (unused; single graph, BN over all nodes)
    const float* eps = (const float*)d_in[3];
    const float* W1  = (const float*)d_in[4];
    const float* b1  = (const float*)d_in[5];
    const float* g1  = (const float*)d_in[6];
    const float* be1 = (const float*)d_in[7];
    const float* W2  = (const float*)d_in[8];
    const float* b2  = (const float*)d_in[9];
    const float* g2  = (const float*)d_in[10];
    const float* be2 = (const float*)d_in[11];
    float* out = (float*)d_out;

    int N = in_sizes[0] / 128;
    int E = in_sizes[1] / 2;
    int n4 = N * 32;
    double invM = 1.0 / (double)N;

    cudaFuncSetAttribute(mma_gemm<0>, cudaFuncAttributeMaxDynamicSharedMemorySize, MMA_SMEM_BYTES);
    cudaFuncSetAttribute(mma_gemm<1>, cudaFuncAttributeMaxDynamicSharedMemorySize, MMA_SMEM_BYTES);

    prep_kernel<<<1, 512>>>(ei, E, N);
    init_h_kernel<<<(n4 + 255) / 256, 256>>>(x, eps, n4);
    scatter_kernel<<<(E + 63) / 64, 256>>>(x, ei, E);

    int gblocks = (N + 127) / 128;
    mma_gemm<0><<<gblocks, 1024, MMA_SMEM_BYTES>>>(W1, b1, nullptr, nullptr, nullptr, invM, N);
    mma_gemm<1><<<gblocks, 1024, MMA_SMEM_BYTES>>>(W2, b2, g1, be1, out, invM, N);
    bn_relu_out_kernel<<<888, 256>>>(out, g2, be2, invM, n4);
}

// round 13
// speedup vs baseline: 1.3052x; 1.3052x over previous
#include <cuda_runtime.h>
#include <cuda_fp16.h>
#include <cstdint>

#define NNODES 50000
#define DFEAT 128

// ---- scratch (device globals: no allocation allowed) ----
__device__ __align__(256) float  g_H[NNODES * DFEAT];   // h = (1+eps)*x + agg
__device__ __align__(256) float  g_Z1[NNODES * DFEAT];  // pre-BN output of linear1
__device__ __align__(256) double g_stats[512];          // sum1,sq1,sum2,sq2 (128 each)
__device__ int g_is64;                                  // edge_index dtype flag

// ============================ small kernels ============================

// zero stats + probe edge dtype. One block, 512 threads.
__global__ void prep_kernel(const void* eiv, int E, int N) {
    int t = threadIdx.x;
    g_stats[t] = 0.0;
    __shared__ int bad;
    if (t == 0) bad = 0;
    __syncthreads();
    const long long* p = (const long long*)eiv;
    int n = E < 1024 ? E : 1024;
    for (int i = t; i < n; i += blockDim.x) {
        long long v = p[i];
        if (v < 0 || v >= (long long)N) atomicOr(&bad, 1);
    }
    __syncthreads();
    if (t == 0) g_is64 = bad ? 0 : 1;
}

// h = (1+eps) * x
__global__ void init_h_kernel(const float* __restrict__ x, const float* __restrict__ eps, int n4) {
    int idx = blockIdx.x * blockDim.x + threadIdx.x;
    if (idx >= n4) return;
    float c = 1.0f + *eps;
    float4 v = ((const float4*)x)[idx];
    v.x *= c; v.y *= c; v.z *= c; v.w *= c;
    ((float4*)g_H)[idx] = v;
}

// edge scatter-add: 8 edges per warp (MLP=8), vector L2 reductions
__global__ void __launch_bounds__(256) scatter_kernel(const float* __restrict__ x,
                                                      const void* __restrict__ eiv, int E) {
    int lane = threadIdx.x & 31;
    int warp = (blockIdx.x * blockDim.x + threadIdx.x) >> 5;
    int e0 = warp * 8;
    if (e0 >= E) return;
    int is64 = g_is64;

    if (e0 + 8 <= E) {
        long long s[8], d[8];
        if (is64) {
            const long long* ei = (const long long*)eiv;
#pragma unroll
            for (int k = 0; k < 8; k++) { s[k] = __ldg(&ei[e0 + k]); d[k] = __ldg(&ei[E + e0 + k]); }
        } else {
            const int* ei = (const int*)eiv;
#pragma unroll
            for (int k = 0; k < 8; k++) { s[k] = __ldg(&ei[e0 + k]); d[k] = __ldg(&ei[E + e0 + k]); }
        }
        float4 v[8];
#pragma unroll
        for (int k = 0; k < 8; k++)
            v[k] = __ldg(((const float4*)(x + s[k] * 128)) + lane);
#pragma unroll
        for (int k = 0; k < 8; k++) {
            float* dp = g_H + d[k] * 128 + (lane << 2);
            asm volatile("red.global.add.v4.f32 [%0], {%1,%2,%3,%4};"
                         :: "l"(dp), "f"(v[k].x), "f"(v[k].y), "f"(v[k].z), "f"(v[k].w) : "memory");
        }
    } else {
        for (int e = e0; e < E; e++) {
            long long s, d;
            if (is64) {
                const long long* ei = (const long long*)eiv;
                s = __ldg(&ei[e]); d = __ldg(&ei[E + e]);
            } else {
                const int* ei = (const int*)eiv;
                s = __ldg(&ei[e]); d = __ldg(&ei[E + e]);
            }
            float4 v = __ldg(((const float4*)(x + s * 128)) + lane);
            float* dp = g_H + d * 128 + (lane << 2);
            asm volatile("red.global.add.v4.f32 [%0], {%1,%2,%3,%4};"
                         :: "l"(dp), "f"(v.x), "f"(v.y), "f"(v.z), "f"(v.w) : "memory");
        }
    }
}

// ============================ fp16 mma.sync GEMM ============================
// Z[m][n] = bias[n] + sum_k f(A[m][k]) * W[n][k], fp16 inputs / fp32 accum.
// fp16 keeps tf32's 10 mantissa bits (same 2^-11 rounding) but k16 mma halves
// both instruction count and LDS traffic (2 fp16 per register).
// MODE 0: A=g_H,  f=identity,                          Z=g_Z1
// MODE 1: A=g_Z1, f=relu(bn1(.)), bn1 finalized inline, Z=Zout
// Block: 128x128 tile, K=128 in smem as packed half2 (row stride 68 uint32:
// fragment banks = 4g+t, all 32 distinct -> conflict-free).
// 512 threads = 16 warps in 4(m) x 4(n); warp tile 32x32; mma.m16n8k16.f16.
// Register double-buffered fragments; column sum/sumsq fused in epilogue.
#define MMA_SMEM_U32 (640 + 2 * 128 * 68)
#define MMA_SMEM_BYTES (MMA_SMEM_U32 * 4)

__device__ __forceinline__ void mma_f16_16n8k16(float c[4], const uint32_t a[4],
                                                uint32_t b0, uint32_t b1) {
    asm volatile(
        "mma.sync.aligned.m16n8k16.row.col.f32.f16.f16.f32 "
        "{%0,%1,%2,%3}, {%4,%5,%6,%7}, {%8,%9}, {%0,%1,%2,%3};"
        : "+f"(c[0]), "+f"(c[1]), "+f"(c[2]), "+f"(c[3])
        : "r"(a[0]), "r"(a[1]), "r"(a[2]), "r"(a[3]), "r"(b0), "r"(b1));
}

__device__ __forceinline__ uint32_t pack_h2(float x, float y) {
    __half2 h = __floats2half2_rn(x, y);
    return *(uint32_t*)&h;
}

template <int MODE>
__global__ void __launch_bounds__(512) mma_gemm(const float* __restrict__ Wmat,
                                                const float* __restrict__ bias,
                                                const float* __restrict__ gamma,
                                                const float* __restrict__ beta,
                                                float* __restrict__ Zout,
                                                double invM, int M) {
    extern __shared__ float sm[];
    float* s_bias  = sm;
    float* s_scale = sm + 128;
    float* s_shift = sm + 256;
    float* s_sum   = sm + 384;
    float* s_sq    = sm + 512;
    uint32_t* As16 = (uint32_t*)(sm + 640);        // [128][68] packed half2
    uint32_t* Bs16 = As16 + 128 * 68;              // [128][68] packed half2, [n][k]

    const float* A = MODE ? g_Z1 : g_H;
    float* Z       = MODE ? Zout : g_Z1;

    int tid = threadIdx.x;
    int m0 = blockIdx.x * 128;

    if (tid < 128) {
        s_bias[tid] = bias[tid];
        s_sum[tid] = 0.f;
        s_sq[tid]  = 0.f;
        if (MODE) {
            // inline BN1 finalize from g_stats (mul-only, invM precomputed on host)
            double mean = g_stats[tid] * invM;
            double var  = g_stats[128 + tid] * invM - mean * mean;
            float sc = gamma[tid] * rsqrtf((float)var + 1e-5f);
            s_scale[tid] = sc;
            s_shift[tid] = beta[tid] - (float)mean * sc;
        }
    }
    __syncthreads();

    // load B (=W, [n][k] natural layout), fp16-packed (4096 float4)
#pragma unroll
    for (int i = 0; i < 8; i++) {
        int idx = i * 512 + tid;
        int n = idx >> 5, k4 = idx & 31;
        float4 v = __ldg(((const float4*)Wmat) + idx);
        *(uint2*)(Bs16 + n * 68 + k4 * 2) =
            make_uint2(pack_h2(v.x, v.y), pack_h2(v.z, v.w));
    }
    // load A tile (fused bn1+relu in MODE 1), fp16-packed
#pragma unroll
    for (int i = 0; i < 8; i++) {
        int idx = i * 512 + tid;
        int m = idx >> 5, k4 = idx & 31;
        int gm = m0 + m;
        float4 v = make_float4(0.f, 0.f, 0.f, 0.f);
        if (gm < M) v = __ldg(((const float4*)A) + (size_t)gm * 32 + k4);
        if (MODE) {
            int k = k4 * 4;
            v.x = fmaxf(fmaf(v.x, s_scale[k + 0], s_shift[k + 0]), 0.f);
            v.y = fmaxf(fmaf(v.y, s_scale[k + 1], s_shift[k + 1]), 0.f);
            v.z = fmaxf(fmaf(v.z, s_scale[k + 2], s_shift[k + 2]), 0.f);
            v.w = fmaxf(fmaf(v.w, s_scale[k + 3], s_shift[k + 3]), 0.f);
        }
        *(uint2*)(As16 + m * 68 + k4 * 2) =
            make_uint2(pack_h2(v.x, v.y), pack_h2(v.z, v.w));
    }
    __syncthreads();

    int lane = tid & 31;
    int wid  = tid >> 5;                   // 0..15
    int g = lane >> 2, t = lane & 3;
    int wm = wid >> 2;                     // 0..3
    int wn = wid & 3;                      // 0..3
    int arow = wm * 32;                    // warp's A row base (in tile)
    int bcol = wn * 32;                    // warp's B col base (in tile)

    float acc[2][4][4];
#pragma unroll
    for (int mt = 0; mt < 2; mt++)
#pragma unroll
        for (int nt = 0; nt < 4; nt++)
#pragma unroll
            for (int q = 0; q < 4; q++) acc[mt][nt][q] = 0.f;

    // double-buffered fragments (uint32 = half2)
    uint32_t a[2][2][4];
    uint32_t b[2][4][2];

    // fragment addressing: k-step ks covers k = ks*16..ks*16+15 -> uint32 j = ks*8..
    // a0:(g, j+t) a1:(g+8, j+t) a2:(g, j+4+t) a3:(g+8, j+4+t); b likewise on [n][k].
#define LOAD_FRAG(ks, buf)                                                   \
    do {                                                                     \
        int _j = (ks) * 8;                                                   \
        _Pragma("unroll")                                                    \
        for (int mt = 0; mt < 2; mt++) {                                     \
            int rb = arow + mt * 16;                                         \
            a[buf][mt][0] = As16[(rb + g) * 68 + _j + t];                    \
            a[buf][mt][1] = As16[(rb + g + 8) * 68 + _j + t];                \
            a[buf][mt][2] = As16[(rb + g) * 68 + _j + 4 + t];                \
            a[buf][mt][3] = As16[(rb + g + 8) * 68 + _j + 4 + t];            \
        }                                                                    \
        _Pragma("unroll")                                                    \
        for (int nt = 0; nt < 4; nt++) {                                     \
            b[buf][nt][0] = Bs16[(bcol + nt * 8 + g) * 68 + _j + t];         \
            b[buf][nt][1] = Bs16[(bcol + nt * 8 + g) * 68 + _j + 4 + t];     \
        }                                                                    \
    } while (0)

    LOAD_FRAG(0, 0);
#pragma unroll
    for (int ks = 0; ks < 8; ks++) {
        int cur = ks & 1;
        if (ks < 7) LOAD_FRAG(ks + 1, cur ^ 1);
#pragma unroll
        for (int nt = 0; nt < 4; nt++) {
            mma_f16_16n8k16(acc[0][nt], a[cur][0], b[cur][nt][0], b[cur][nt][1]);
            mma_f16_16n8k16(acc[1][nt], a[cur][1], b[cur][nt][0], b[cur][nt][1]);
        }
    }
#undef LOAD_FRAG

    // epilogue: bias add, store float2 pairs, fused column stats
#pragma unroll
    for (int nt = 0; nt < 4; nt++) {
        int col = bcol + nt * 8 + 2 * t;
        float bi0 = s_bias[col], bi1 = s_bias[col + 1];
        float cs0 = 0.f, cq0 = 0.f, cs1 = 0.f, cq1 = 0.f;
#pragma unroll
        for (int mt = 0; mt < 2; mt++) {
#pragma unroll
            for (int rr = 0; rr < 2; rr++) {
                int gm = m0 + arow + mt * 16 + g + rr * 8;
                if (gm < M) {
                    float o0 = acc[mt][nt][rr * 2 + 0] + bi0;
                    float o1 = acc[mt][nt][rr * 2 + 1] + bi1;
                    *(float2*)(Z + (size_t)gm * 128 + col) = make_float2(o0, o1);
                    cs0 += o0; cq0 += o0 * o0;
                    cs1 += o1; cq1 += o1 * o1;
                }
            }
        }
        atomicAdd(&s_sum[col], cs0);     atomicAdd(&s_sq[col], cq0);
        atomicAdd(&s_sum[col + 1], cs1); atomicAdd(&s_sq[col + 1], cq1);
    }
    __syncthreads();
    if (tid < 128) {
        double* sum = g_stats + (MODE ? 256 : 0);
        double* sq  = g_stats + (MODE ? 384 : 128);
        atomicAdd(&sum[tid], (double)s_sum[tid]);
        atomicAdd(&sq[tid],  (double)s_sq[tid]);
    }
}

// ---- final: out = relu(bn2(out)) in place; BN2 finalize inlined (mul-only),
//      grid-stride so only ~888 blocks recompute it ----
__global__ void bn_relu_out_kernel(float* __restrict__ out,
                                   const float* __restrict__ gamma,
                                   const float* __restrict__ beta,
                                   double invM, int n4) {
    __shared__ float sc[128], sh[128];
    int t = threadIdx.x;
    if (t < 128) {
        double mean = g_stats[256 + t] * invM;
        double var  = g_stats[384 + t] * invM - mean * mean;
        float s = gamma[t] * rsqrtf((float)var + 1e-5f);
        sc[t] = s;
        sh[t] = beta[t] - (float)mean * s;
    }
    __syncthreads();
    for (int idx = blockIdx.x * blockDim.x + t; idx < n4; idx += gridDim.x * blockDim.x) {
        float4 v = ((float4*)out)[idx];
        int k = (idx & 31) * 4;
        v.x = fmaxf(fmaf(v.x, sc[k + 0], sh[k + 0]), 0.f);
        v.y = fmaxf(fmaf(v.y, sc[k + 1], sh[k + 1]), 0.f);
        v.z = fmaxf(fmaf(v.z, sc[k + 2], sh[k + 2]), 0.f);
        v.w = fmaxf(fmaf(v.w, sc[k + 3], sh[k + 3]), 0.f);
        ((float4*)out)[idx] = v;
    }
}

extern "C" void kernel_launch(void* const* d_in, const int* in_sizes, int n_in,
                              void* d_out, int out_size) {
    const float* x   = (const float*)d_in[0];
    const void*  ei  = d_in[1];
    // d_in[2] = batch (unused; single graph, BN over all nodes)
    const float* eps = (const float*)d_in[3];
    const float* W1  = (const float*)d_in[4];
    const float* b1  = (const float*)d_in[5];
    const float* g1  = (const float*)d_in[6];
    const float* be1 = (const float*)d_in[7];
    const float* W2  = (const float*)d_in[8];
    const float* b2  = (const float*)d_in[9];
    const float* g2  = (const float*)d_in[10];
    const float* be2 = (const float*)d_in[11];
    float* out = (float*)d_out;

    int N = in_sizes[0] / 128;
    int E = in_sizes[1] / 2;
    int n4 = N * 32;
    double invM = 1.0 / (double)N;

    cudaFuncSetAttribute(mma_gemm<0>, cudaFuncAttributeMaxDynamicSharedMemorySize, MMA_SMEM_BYTES);
    cudaFuncSetAttribute(mma_gemm<1>, cudaFuncAttributeMaxDynamicSharedMemorySize, MMA_SMEM_BYTES);

    prep_kernel<<<1, 512>>>(ei, E, N);
    init_h_kernel<<<(n4 + 255) / 256, 256>>>(x, eps, n4);
    scatter_kernel<<<(E + 63) / 64, 256>>>(x, ei, E);

    int gblocks = (N + 127) / 128;
    mma_gemm<0><<<gblocks, 512, MMA_SMEM_BYTES>>>(W1, b1, nullptr, nullptr, nullptr, invM, N);
    mma_gemm<1><<<gblocks, 512, MMA_SMEM_BYTES>>>(W2, b2, g1, be1, out, invM, N);
    bn_relu_out_kernel<<<888, 256>>>(out, g2, be2, invM, n4);
}

// round 14
// speedup vs baseline: 1.3130x; 1.0060x over previous
#include <cuda_runtime.h>
#include <cuda_fp16.h>
#include <cstdint>

#define NNODES 50000
#define DFEAT 128

// ---- scratch (device globals: no allocation allowed) ----
__device__ __align__(256) float  g_H[NNODES * DFEAT];   // h = (1+eps)*x + agg
__device__ __align__(256) float  g_Z1[NNODES * DFEAT];  // pre-BN output of linear1
__device__ __align__(256) __half g_Xh[NNODES * DFEAT];  // fp16 mirror of x (gather source)
__device__ __align__(256) double g_stats[512];          // sum1,sq1,sum2,sq2 (128 each)
__device__ int g_is64;                                  // edge_index dtype flag

// ============================ small kernels ============================

// zero stats + probe edge dtype. One block, 512 threads.
__global__ void prep_kernel(const void* eiv, int E, int N) {
    int t = threadIdx.x;
    g_stats[t] = 0.0;
    __shared__ int bad;
    if (t == 0) bad = 0;
    __syncthreads();
    const long long* p = (const long long*)eiv;
    int n = E < 1024 ? E : 1024;
    for (int i = t; i < n; i += blockDim.x) {
        long long v = p[i];
        if (v < 0 || v >= (long long)N) atomicOr(&bad, 1);
    }
    __syncthreads();
    if (t == 0) g_is64 = bad ? 0 : 1;
}

// fused: g_H = (1+eps)*x (fp32)  AND  g_Xh = fp16(x)
__global__ void convert_init_kernel(const float* __restrict__ x,
                                    const float* __restrict__ eps, int n4) {
    int idx = blockIdx.x * blockDim.x + threadIdx.x;
    if (idx >= n4) return;
    float c = 1.0f + *eps;
    float4 v = ((const float4*)x)[idx];
    __half2 h0 = __floats2half2_rn(v.x, v.y);
    __half2 h1 = __floats2half2_rn(v.z, v.w);
    ((uint2*)g_Xh)[idx] = make_uint2(*(uint32_t*)&h0, *(uint32_t*)&h1);
    ((float4*)g_H)[idx] = make_float4(v.x * c, v.y * c, v.z * c, v.w * c);
}

// edge scatter-add: 8 edges per warp (MLP=8); gather fp16 (half the read
// bytes), accumulate with fp32 vector L2 reductions (precision preserved).
__global__ void __launch_bounds__(256) scatter_kernel(const void* __restrict__ eiv, int E) {
    int lane = threadIdx.x & 31;
    int warp = (blockIdx.x * blockDim.x + threadIdx.x) >> 5;
    int e0 = warp * 8;
    if (e0 >= E) return;
    int is64 = g_is64;

    if (e0 + 8 <= E) {
        long long s[8], d[8];
        if (is64) {
            const long long* ei = (const long long*)eiv;
#pragma unroll
            for (int k = 0; k < 8; k++) { s[k] = __ldg(&ei[e0 + k]); d[k] = __ldg(&ei[E + e0 + k]); }
        } else {
            const int* ei = (const int*)eiv;
#pragma unroll
            for (int k = 0; k < 8; k++) { s[k] = __ldg(&ei[e0 + k]); d[k] = __ldg(&ei[E + e0 + k]); }
        }
        uint2 hv[8];
#pragma unroll
        for (int k = 0; k < 8; k++)
            hv[k] = __ldg(((const uint2*)(g_Xh + s[k] * 128)) + lane);
#pragma unroll
        for (int k = 0; k < 8; k++) {
            float2 f0 = __half22float2(*(__half2*)&hv[k].x);
            float2 f1 = __half22float2(*(__half2*)&hv[k].y);
            float* dp = g_H + d[k] * 128 + (lane << 2);
            asm volatile("red.global.add.v4.f32 [%0], {%1,%2,%3,%4};"
                         :: "l"(dp), "f"(f0.x), "f"(f0.y), "f"(f1.x), "f"(f1.y) : "memory");
        }
    } else {
        for (int e = e0; e < E; e++) {
            long long s, d;
            if (is64) {
                const long long* ei = (const long long*)eiv;
                s = __ldg(&ei[e]); d = __ldg(&ei[E + e]);
            } else {
                const int* ei = (const int*)eiv;
                s = __ldg(&ei[e]); d = __ldg(&ei[E + e]);
            }
            uint2 hv = __ldg(((const uint2*)(g_Xh + s * 128)) + lane);
            float2 f0 = __half22float2(*(__half2*)&hv.x);
            float2 f1 = __half22float2(*(__half2*)&hv.y);
            float* dp = g_H + d * 128 + (lane << 2);
            asm volatile("red.global.add.v4.f32 [%0], {%1,%2,%3,%4};"
                         :: "l"(dp), "f"(f0.x), "f"(f0.y), "f"(f1.x), "f"(f1.y) : "memory");
        }
    }
}

// ============================ fp16 mma.sync GEMM ============================
// Z[m][n] = bias[n] + sum_k f(A[m][k]) * W[n][k], fp16 inputs / fp32 accum.
// MODE 0: A=g_H,  f=identity,                          Z=g_Z1
// MODE 1: A=g_Z1, f=relu(bn1(.)), bn1 finalized inline, Z=Zout
// Block: 128x128 tile, K=128 in smem as packed half2 (row stride 68 uint32:
// fragment banks = 4g+t, all 32 distinct -> conflict-free).
// 512 threads = 16 warps in 4(m) x 4(n); warp tile 32x32; mma.m16n8k16.f16.
// Register double-buffered fragments; column sum/sumsq fused in epilogue.
#define MMA_SMEM_U32 (640 + 2 * 128 * 68)
#define MMA_SMEM_BYTES (MMA_SMEM_U32 * 4)

__device__ __forceinline__ void mma_f16_16n8k16(float c[4], const uint32_t a[4],
                                                uint32_t b0, uint32_t b1) {
    asm volatile(
        "mma.sync.aligned.m16n8k16.row.col.f32.f16.f16.f32 "
        "{%0,%1,%2,%3}, {%4,%5,%6,%7}, {%8,%9}, {%0,%1,%2,%3};"
        : "+f"(c[0]), "+f"(c[1]), "+f"(c[2]), "+f"(c[3])
        : "r"(a[0]), "r"(a[1]), "r"(a[2]), "r"(a[3]), "r"(b0), "r"(b1));
}

__device__ __forceinline__ uint32_t pack_h2(float x, float y) {
    __half2 h = __floats2half2_rn(x, y);
    return *(uint32_t*)&h;
}

template <int MODE>
__global__ void __launch_bounds__(512) mma_gemm(const float* __restrict__ Wmat,
                                                const float* __restrict__ bias,
                                                const float* __restrict__ gamma,
                                                const float* __restrict__ beta,
                                                float* __restrict__ Zout,
                                                double invM, int M) {
    extern __shared__ float sm[];
    float* s_bias  = sm;
    float* s_scale = sm + 128;
    float* s_shift = sm + 256;
    float* s_sum   = sm + 384;
    float* s_sq    = sm + 512;
    uint32_t* As16 = (uint32_t*)(sm + 640);        // [128][68] packed half2
    uint32_t* Bs16 = As16 + 128 * 68;              // [128][68] packed half2, [n][k]

    const float* A = MODE ? g_Z1 : g_H;
    float* Z       = MODE ? Zout : g_Z1;

    int tid = threadIdx.x;
    int m0 = blockIdx.x * 128;

    if (tid < 128) {
        s_bias[tid] = bias[tid];
        s_sum[tid] = 0.f;
        s_sq[tid]  = 0.f;
        if (MODE) {
            // inline BN1 finalize from g_stats (mul-only, invM precomputed on host)
            double mean = g_stats[tid] * invM;
            double var  = g_stats[128 + tid] * invM - mean * mean;
            float sc = gamma[tid] * rsqrtf((float)var + 1e-5f);
            s_scale[tid] = sc;
            s_shift[tid] = beta[tid] - (float)mean * sc;
        }
    }
    __syncthreads();

    // load B (=W, [n][k] natural layout), fp16-packed (4096 float4)
#pragma unroll
    for (int i = 0; i < 8; i++) {
        int idx = i * 512 + tid;
        int n = idx >> 5, k4 = idx & 31;
        float4 v = __ldg(((const float4*)Wmat) + idx);
        *(uint2*)(Bs16 + n * 68 + k4 * 2) =
            make_uint2(pack_h2(v.x, v.y), pack_h2(v.z, v.w));
    }
    // load A tile (fused bn1+relu in MODE 1), fp16-packed
#pragma unroll
    for (int i = 0; i < 8; i++) {
        int idx = i * 512 + tid;
        int m = idx >> 5, k4 = idx & 31;
        int gm = m0 + m;
        float4 v = make_float4(0.f, 0.f, 0.f, 0.f);
        if (gm < M) v = __ldg(((const float4*)A) + (size_t)gm * 32 + k4);
        if (MODE) {
            int k = k4 * 4;
            v.x = fmaxf(fmaf(v.x, s_scale[k + 0], s_shift[k + 0]), 0.f);
            v.y = fmaxf(fmaf(v.y, s_scale[k + 1], s_shift[k + 1]), 0.f);
            v.z = fmaxf(fmaf(v.z, s_scale[k + 2], s_shift[k + 2]), 0.f);
            v.w = fmaxf(fmaf(v.w, s_scale[k + 3], s_shift[k + 3]), 0.f);
        }
        *(uint2*)(As16 + m * 68 + k4 * 2) =
            make_uint2(pack_h2(v.x, v.y), pack_h2(v.z, v.w));
    }
    __syncthreads();

    int lane = tid & 31;
    int wid  = tid >> 5;                   // 0..15
    int g = lane >> 2, t = lane & 3;
    int wm = wid >> 2;                     // 0..3
    int wn = wid & 3;                      // 0..3
    int arow = wm * 32;                    // warp's A row base (in tile)
    int bcol = wn * 32;                    // warp's B col base (in tile)

    float acc[2][4][4];
#pragma unroll
    for (int mt = 0; mt < 2; mt++)
#pragma unroll
        for (int nt = 0; nt < 4; nt++)
#pragma unroll
            for (int q = 0; q < 4; q++) acc[mt][nt][q] = 0.f;

    // double-buffered fragments (uint32 = half2)
    uint32_t a[2][2][4];
    uint32_t b[2][4][2];

#define LOAD_FRAG(ks, buf)                                                   \
    do {                                                                     \
        int _j = (ks) * 8;                                                   \
        _Pragma("unroll")                                                    \
        for (int mt = 0; mt < 2; mt++) {                                     \
            int rb = arow + mt * 16;                                         \
            a[buf][mt][0] = As16[(rb + g) * 68 + _j + t];                    \
            a[buf][mt][1] = As16[(rb + g + 8) * 68 + _j + t];                \
            a[buf][mt][2] = As16[(rb + g) * 68 + _j + 4 + t];                \
            a[buf][mt][3] = As16[(rb + g + 8) * 68 + _j + 4 + t];            \
        }                                                                    \
        _Pragma("unroll")                                                    \
        for (int nt = 0; nt < 4; nt++) {                                     \
            b[buf][nt][0] = Bs16[(bcol + nt * 8 + g) * 68 + _j + t];         \
            b[buf][nt][1] = Bs16[(bcol + nt * 8 + g) * 68 + _j + 4 + t];     \
        }                                                                    \
    } while (0)

    LOAD_FRAG(0, 0);
#pragma unroll
    for (int ks = 0; ks < 8; ks++) {
        int cur = ks & 1;
        if (ks < 7) LOAD_FRAG(ks + 1, cur ^ 1);
#pragma unroll
        for (int nt = 0; nt < 4; nt++) {
            mma_f16_16n8k16(acc[0][nt], a[cur][0], b[cur][nt][0], b[cur][nt][1]);
            mma_f16_16n8k16(acc[1][nt], a[cur][1], b[cur][nt][0], b[cur][nt][1]);
        }
    }
#undef LOAD_FRAG

    // epilogue: bias add, store float2 pairs, fused column stats
#pragma unroll
    for (int nt = 0; nt < 4; nt++) {
        int col = bcol + nt * 8 + 2 * t;
        float bi0 = s_bias[col], bi1 = s_bias[col + 1];
        float cs0 = 0.f, cq0 = 0.f, cs1 = 0.f, cq1 = 0.f;
#pragma unroll
        for (int mt = 0; mt < 2; mt++) {
#pragma unroll
            for (int rr = 0; rr < 2; rr++) {
                int gm = m0 + arow + mt * 16 + g + rr * 8;
                if (gm < M) {
                    float o0 = acc[mt][nt][rr * 2 + 0] + bi0;
                    float o1 = acc[mt][nt][rr * 2 + 1] + bi1;
                    *(float2*)(Z + (size_t)gm * 128 + col) = make_float2(o0, o1);
                    cs0 += o0; cq0 += o0 * o0;
                    cs1 += o1; cq1 += o1 * o1;
                }
            }
        }
        atomicAdd(&s_sum[col], cs0);     atomicAdd(&s_sq[col], cq0);
        atomicAdd(&s_sum[col + 1], cs1); atomicAdd(&s_sq[col + 1], cq1);
    }
    __syncthreads();
    if (tid < 128) {
        double* sum = g_stats + (MODE ? 256 : 0);
        double* sq  = g_stats + (MODE ? 384 : 128);
        atomicAdd(&sum[tid], (double)s_sum[tid]);
        atomicAdd(&sq[tid],  (double)s_sq[tid]);
    }
}

// ---- final: out = relu(bn2(out)) in place; BN2 finalize inlined (mul-only),
//      grid-stride so only ~888 blocks recompute it ----
__global__ void bn_relu_out_kernel(float* __restrict__ out,
                                   const float* __restrict__ gamma,
                                   const float* __restrict__ beta,
                                   double invM, int n4) {
    __shared__ float sc[128], sh[128];
    int t = threadIdx.x;
    if (t < 128) {
        double mean = g_stats[256 + t] * invM;
        double var  = g_stats[384 + t] * invM - mean * mean;
        float s = gamma[t] * rsqrtf((float)var + 1e-5f);
        sc[t] = s;
        sh[t] = beta[t] - (float)mean * s;
    }
    __syncthreads();
    for (int idx = blockIdx.x * blockDim.x + t; idx < n4; idx += gridDim.x * blockDim.x) {
        float4 v = ((float4*)out)[idx];
        int k = (idx & 31) * 4;
        v.x = fmaxf(fmaf(v.x, sc[k + 0], sh[k + 0]), 0.f);
        v.y = fmaxf(fmaf(v.y, sc[k + 1], sh[k + 1]), 0.f);
        v.z = fmaxf(fmaf(v.z, sc[k + 2], sh[k + 2]), 0.f);
        v.w = fmaxf(fmaf(v.w, sc[k + 3], sh[k + 3]), 0.f);
        ((float4*)out)[idx] = v;
    }
}

extern "C" void kernel_launch(void* const* d_in, const int* in_sizes, int n_in,
                              void* d_out, int out_size) {
    const float* x   = (const float*)d_in[0];
    const void*  ei  = d_in[1];
    // d_in[2] = batch (unused; single graph, BN over all nodes)
    const float* eps = (const float*)d_in[3];
    const float* W1  = (const float*)d_in[4];
    const float* b1  = (const float*)d_in[5];
    const float* g1  = (const float*)d_in[6];
    const float* be1 = (const float*)d_in[7];
    const float* W2  = (const float*)d_in[8];
    const float* b2  = (const float*)d_in[9];
    const float* g2  = (const float*)d_in[10];
    const float* be2 = (const float*)d_in[11];
    float* out = (float*)d_out;

    int N = in_sizes[0] / 128;
    int E = in_sizes[1] / 2;
    int n4 = N * 32;
    double invM = 1.0 / (double)N;

    cudaFuncSetAttribute(mma_gemm<0>, cudaFuncAttributeMaxDynamicSharedMemorySize, MMA_SMEM_BYTES);
    cudaFuncSetAttribute(mma_gemm<1>, cudaFuncAttributeMaxDynamicSharedMemorySize, MMA_SMEM_BYTES);

    prep_kernel<<<1, 512>>>(ei, E, N);
    convert_init_kernel<<<(n4 + 255) / 256, 256>>>(x, eps, n4);
    scatter_kernel<<<(E + 63) / 64, 256>>>(ei, E);

    int gblocks = (N + 127) / 128;
    mma_gemm<0><<<gblocks, 512, MMA_SMEM_BYTES>>>(W1, b1, nullptr, nullptr, nullptr, invM, N);
    mma_gemm<1><<<gblocks, 512, MMA_SMEM_BYTES>>>(W2, b2, g1, be1, out, invM, N);
    bn_relu_out_kernel<<<888, 256>>>(out, g2, be2, invM, n4);
}

// round 15
// speedup vs baseline: 1.3242x; 1.0085x over previous
#include <cuda_runtime.h>
#include <cuda_fp16.h>
#include <cstdint>

#define NNODES 50000
#define DFEAT 128

// ---- scratch (device globals: no allocation allowed) ----
__device__ __align__(256) float  g_H[NNODES * DFEAT];   // h = (1+eps)*x + agg
__device__ __align__(256) float  g_Z1[NNODES * DFEAT];  // pre-BN output of linear1
__device__ __align__(256) __half g_Xh[NNODES * DFEAT];  // fp16 mirror of x (gather source)
__device__ __align__(256) double g_stats[512];          // sum1,sq1,sum2,sq2 (128 each)
__device__ int g_is64;                                  // edge_index dtype flag

// ============================ small kernels ============================

// zero stats + probe edge dtype. One block, 512 threads.
__global__ void prep_kernel(const void* eiv, int E, int N) {
    int t = threadIdx.x;
    g_stats[t] = 0.0;
    __shared__ int bad;
    if (t == 0) bad = 0;
    __syncthreads();
    const long long* p = (const long long*)eiv;
    int n = E < 1024 ? E : 1024;
    for (int i = t; i < n; i += blockDim.x) {
        long long v = p[i];
        if (v < 0 || v >= (long long)N) atomicOr(&bad, 1);
    }
    __syncthreads();
    if (t == 0) g_is64 = bad ? 0 : 1;
}

// fused: g_H = (1+eps)*x (fp32)  AND  g_Xh = fp16(x)
__global__ void convert_init_kernel(const float* __restrict__ x,
                                    const float* __restrict__ eps, int n4) {
    int idx = blockIdx.x * blockDim.x + threadIdx.x;
    if (idx >= n4) return;
    float c = 1.0f + *eps;
    float4 v = ((const float4*)x)[idx];
    __half2 h0 = __floats2half2_rn(v.x, v.y);
    __half2 h1 = __floats2half2_rn(v.z, v.w);
    ((uint2*)g_Xh)[idx] = make_uint2(*(uint32_t*)&h0, *(uint32_t*)&h1);
    ((float4*)g_H)[idx] = make_float4(v.x * c, v.y * c, v.z * c, v.w * c);
}

// edge scatter-add: 8 edges per warp (MLP=8); gather fp16 (half the read
// bytes), accumulate with fp32 vector L2 reductions (precision preserved).
__global__ void __launch_bounds__(256) scatter_kernel(const void* __restrict__ eiv, int E) {
    int lane = threadIdx.x & 31;
    int warp = (blockIdx.x * blockDim.x + threadIdx.x) >> 5;
    int e0 = warp * 8;
    if (e0 >= E) return;
    int is64 = g_is64;

    if (e0 + 8 <= E) {
        long long s[8], d[8];
        if (is64) {
            const long long* ei = (const long long*)eiv;
#pragma unroll
            for (int k = 0; k < 8; k++) { s[k] = __ldg(&ei[e0 + k]); d[k] = __ldg(&ei[E + e0 + k]); }
        } else {
            const int* ei = (const int*)eiv;
#pragma unroll
            for (int k = 0; k < 8; k++) { s[k] = __ldg(&ei[e0 + k]); d[k] = __ldg(&ei[E + e0 + k]); }
        }
        uint2 hv[8];
#pragma unroll
        for (int k = 0; k < 8; k++)
            hv[k] = __ldg(((const uint2*)(g_Xh + s[k] * 128)) + lane);
#pragma unroll
        for (int k = 0; k < 8; k++) {
            float2 f0 = __half22float2(*(__half2*)&hv[k].x);
            float2 f1 = __half22float2(*(__half2*)&hv[k].y);
            float* dp = g_H + d[k] * 128 + (lane << 2);
            asm volatile("red.global.add.v4.f32 [%0], {%1,%2,%3,%4};"
                         :: "l"(dp), "f"(f0.x), "f"(f0.y), "f"(f1.x), "f"(f1.y) : "memory");
        }
    } else {
        for (int e = e0; e < E; e++) {
            long long s, d;
            if (is64) {
                const long long* ei = (const long long*)eiv;
                s = __ldg(&ei[e]); d = __ldg(&ei[E + e]);
            } else {
                const int* ei = (const int*)eiv;
                s = __ldg(&ei[e]); d = __ldg(&ei[E + e]);
            }
            uint2 hv = __ldg(((const uint2*)(g_Xh + s * 128)) + lane);
            float2 f0 = __half22float2(*(__half2*)&hv.x);
            float2 f1 = __half22float2(*(__half2*)&hv.y);
            float* dp = g_H + d * 128 + (lane << 2);
            asm volatile("red.global.add.v4.f32 [%0], {%1,%2,%3,%4};"
                         :: "l"(dp), "f"(f0.x), "f"(f0.y), "f"(f1.x), "f"(f1.y) : "memory");
        }
    }
}

// ============================ fp16 mma.sync GEMM ============================
// Z[m][n] = bias[n] + sum_k f(A[m][k]) * W[n][k], fp16 inputs / fp32 accum.
// MODE 0: A=g_H,  f=identity,                          Z=g_Z1
// MODE 1: A=g_Z1, f=relu(bn1(.)), bn1 finalized inline, Z=Zout
// Block: 128x128 tile, K=128 in smem as packed half2 (row stride 68 uint32:
// fragment banks = 4g+t, all 32 distinct -> conflict-free).
// 512 threads = 16 warps in 4(m) x 4(n); warp tile 32x32; mma.m16n8k16.f16.
// fp16 tiles = 72KB smem -> 2 CTAs/SM (8 warps/SMSP) at the SAME tile shape.
// Register double-buffered fragments; column sum/sumsq fused in epilogue.
#define MMA_SMEM_U32 (640 + 2 * 128 * 68)
#define MMA_SMEM_BYTES (MMA_SMEM_U32 * 4)

__device__ __forceinline__ void mma_f16_16n8k16(float c[4], const uint32_t a[4],
                                                uint32_t b0, uint32_t b1) {
    asm volatile(
        "mma.sync.aligned.m16n8k16.row.col.f32.f16.f16.f32 "
        "{%0,%1,%2,%3}, {%4,%5,%6,%7}, {%8,%9}, {%0,%1,%2,%3};"
        : "+f"(c[0]), "+f"(c[1]), "+f"(c[2]), "+f"(c[3])
        : "r"(a[0]), "r"(a[1]), "r"(a[2]), "r"(a[3]), "r"(b0), "r"(b1));
}

__device__ __forceinline__ uint32_t pack_h2(float x, float y) {
    __half2 h = __floats2half2_rn(x, y);
    return *(uint32_t*)&h;
}

template <int MODE>
__global__ void __launch_bounds__(512, 2) mma_gemm(const float* __restrict__ Wmat,
                                                   const float* __restrict__ bias,
                                                   const float* __restrict__ gamma,
                                                   const float* __restrict__ beta,
                                                   float* __restrict__ Zout,
                                                   double invM, int M) {
    extern __shared__ float sm[];
    float* s_bias  = sm;
    float* s_scale = sm + 128;
    float* s_shift = sm + 256;
    float* s_sum   = sm + 384;
    float* s_sq    = sm + 512;
    uint32_t* As16 = (uint32_t*)(sm + 640);        // [128][68] packed half2
    uint32_t* Bs16 = As16 + 128 * 68;              // [128][68] packed half2, [n][k]

    const float* A = MODE ? g_Z1 : g_H;
    float* Z       = MODE ? Zout : g_Z1;

    int tid = threadIdx.x;
    int m0 = blockIdx.x * 128;

    if (tid < 128) {
        s_bias[tid] = bias[tid];
        s_sum[tid] = 0.f;
        s_sq[tid]  = 0.f;
        if (MODE) {
            // inline BN1 finalize from g_stats (mul-only, invM precomputed on host)
            double mean = g_stats[tid] * invM;
            double var  = g_stats[128 + tid] * invM - mean * mean;
            float sc = gamma[tid] * rsqrtf((float)var + 1e-5f);
            s_scale[tid] = sc;
            s_shift[tid] = beta[tid] - (float)mean * sc;
        }
    }
    __syncthreads();

    // load B (=W, [n][k] natural layout), fp16-packed (4096 float4)
#pragma unroll
    for (int i = 0; i < 8; i++) {
        int idx = i * 512 + tid;
        int n = idx >> 5, k4 = idx & 31;
        float4 v = __ldg(((const float4*)Wmat) + idx);
        *(uint2*)(Bs16 + n * 68 + k4 * 2) =
            make_uint2(pack_h2(v.x, v.y), pack_h2(v.z, v.w));
    }
    // load A tile (fused bn1+relu in MODE 1), fp16-packed
#pragma unroll
    for (int i = 0; i < 8; i++) {
        int idx = i * 512 + tid;
        int m = idx >> 5, k4 = idx & 31;
        int gm = m0 + m;
        float4 v = make_float4(0.f, 0.f, 0.f, 0.f);
        if (gm < M) v = __ldg(((const float4*)A) + (size_t)gm * 32 + k4);
        if (MODE) {
            int k = k4 * 4;
            v.x = fmaxf(fmaf(v.x, s_scale[k + 0], s_shift[k + 0]), 0.f);
            v.y = fmaxf(fmaf(v.y, s_scale[k + 1], s_shift[k + 1]), 0.f);
            v.z = fmaxf(fmaf(v.z, s_scale[k + 2], s_shift[k + 2]), 0.f);
            v.w = fmaxf(fmaf(v.w, s_scale[k + 3], s_shift[k + 3]), 0.f);
        }
        *(uint2*)(As16 + m * 68 + k4 * 2) =
            make_uint2(pack_h2(v.x, v.y), pack_h2(v.z, v.w));
    }
    __syncthreads();

    int lane = tid & 31;
    int wid  = tid >> 5;                   // 0..15
    int g = lane >> 2, t = lane & 3;
    int wm = wid >> 2;                     // 0..3
    int wn = wid & 3;                      // 0..3
    int arow = wm * 32;                    // warp's A row base (in tile)
    int bcol = wn * 32;                    // warp's B col base (in tile)

    float acc[2][4][4];
#pragma unroll
    for (int mt = 0; mt < 2; mt++)
#pragma unroll
        for (int nt = 0; nt < 4; nt++)
#pragma unroll
            for (int q = 0; q < 4; q++) acc[mt][nt][q] = 0.f;

    // double-buffered fragments (uint32 = half2)
    uint32_t a[2][2][4];
    uint32_t b[2][4][2];

#define LOAD_FRAG(ks, buf)                                                   \
    do {                                                                     \
        int _j = (ks) * 8;                                                   \
        _Pragma("unroll")                                                    \
        for (int mt = 0; mt < 2; mt++) {                                     \
            int rb = arow + mt * 16;                                         \
            a[buf][mt][0] = As16[(rb + g) * 68 + _j + t];                    \
            a[buf][mt][1] = As16[(rb + g + 8) * 68 + _j + t];                \
            a[buf][mt][2] = As16[(rb + g) * 68 + _j + 4 + t];                \
            a[buf][mt][3] = As16[(rb + g + 8) * 68 + _j + 4 + t];            \
        }                                                                    \
        _Pragma("unroll")                                                    \
        for (int nt = 0; nt < 4; nt++) {                                     \
            b[buf][nt][0] = Bs16[(bcol + nt * 8 + g) * 68 + _j + t];         \
            b[buf][nt][1] = Bs16[(bcol + nt * 8 + g) * 68 + _j + 4 + t];     \
        }                                                                    \
    } while (0)

    LOAD_FRAG(0, 0);
#pragma unroll
    for (int ks = 0; ks < 8; ks++) {
        int cur = ks & 1;
        if (ks < 7) LOAD_FRAG(ks + 1, cur ^ 1);
#pragma unroll
        for (int nt = 0; nt < 4; nt++) {
            mma_f16_16n8k16(acc[0][nt], a[cur][0], b[cur][nt][0], b[cur][nt][1]);
            mma_f16_16n8k16(acc[1][nt], a[cur][1], b[cur][nt][0], b[cur][nt][1]);
        }
    }
#undef LOAD_FRAG

    // epilogue: bias add, store float2 pairs, fused column stats
#pragma unroll
    for (int nt = 0; nt < 4; nt++) {
        int col = bcol + nt * 8 + 2 * t;
        float bi0 = s_bias[col], bi1 = s_bias[col + 1];
        float cs0 = 0.f, cq0 = 0.f, cs1 = 0.f, cq1 = 0.f;
#pragma unroll
        for (int mt = 0; mt < 2; mt++) {
#pragma unroll
            for (int rr = 0; rr < 2; rr++) {
                int gm = m0 + arow + mt * 16 + g + rr * 8;
                if (gm < M) {
                    float o0 = acc[mt][nt][rr * 2 + 0] + bi0;
                    float o1 = acc[mt][nt][rr * 2 + 1] + bi1;
                    *(float2*)(Z + (size_t)gm * 128 + col) = make_float2(o0, o1);
                    cs0 += o0; cq0 += o0 * o0;
                    cs1 += o1; cq1 += o1 * o1;
                }
            }
        }
        atomicAdd(&s_sum[col], cs0);     atomicAdd(&s_sq[col], cq0);
        atomicAdd(&s_sum[col + 1], cs1); atomicAdd(&s_sq[col + 1], cq1);
    }
    __syncthreads();
    if (tid < 128) {
        double* sum = g_stats + (MODE ? 256 : 0);
        double* sq  = g_stats + (MODE ? 384 : 128);
        atomicAdd(&sum[tid], (double)s_sum[tid]);
        atomicAdd(&sq[tid],  (double)s_sq[tid]);
    }
}

// ---- final: out = relu(bn2(out)) in place; BN2 finalize inlined (mul-only),
//      grid-stride so only ~888 blocks recompute it ----
__global__ void bn_relu_out_kernel(float* __restrict__ out,
                                   const float* __restrict__ gamma,
                                   const float* __restrict__ beta,
                                   double invM, int n4) {
    __shared__ float sc[128], sh[128];
    int t = threadIdx.x;
    if (t < 128) {
        double mean = g_stats[256 + t] * invM;
        double var  = g_stats[384 + t] * invM - mean * mean;
        float s = gamma[t] * rsqrtf((float)var + 1e-5f);
        sc[t] = s;
        sh[t] = beta[t] - (float)mean * s;
    }
    __syncthreads();
    for (int idx = blockIdx.x * blockDim.x + t; idx < n4; idx += gridDim.x * blockDim.x) {
        float4 v = ((float4*)out)[idx];
        int k = (idx & 31) * 4;
        v.x = fmaxf(fmaf(v.x, sc[k + 0], sh[k + 0]), 0.f);
        v.y = fmaxf(fmaf(v.y, sc[k + 1], sh[k + 1]), 0.f);
        v.z = fmaxf(fmaf(v.z, sc[k + 2], sh[k + 2]), 0.f);
        v.w = fmaxf(fmaf(v.w, sc[k + 3], sh[k + 3]), 0.f);
        ((float4*)out)[idx] = v;
    }
}

extern "C" void kernel_launch(void* const* d_in, const int* in_sizes, int n_in,
                              void* d_out, int out_size) {
    const float* x   = (const float*)d_in[0];
    const void*  ei  = d_in[1];
    // d_in[2] = batch (unused; single graph, BN over all nodes)
    const float* eps = (const float*)d_in[3];
    const float* W1  = (const float*)d_in[4];
    const float* b1  = (const float*)d_in[5];
    const float* g1  = (const float*)d_in[6];
    const float* be1 = (const float*)d_in[7];
    const float* W2  = (const float*)d_in[8];
    const float* b2  = (const float*)d_in[9];
    const float* g2  = (const float*)d_in[10];
    const float* be2 = (const float*)d_in[11];
    float* out = (float*)d_out;

    int N = in_sizes[0] / 128;
    int E = in_sizes[1] / 2;
    int n4 = N * 32;
    double invM = 1.0 / (double)N;

    cudaFuncSetAttribute(mma_gemm<0>, cudaFuncAttributeMaxDynamicSharedMemorySize, MMA_SMEM_BYTES);
    cudaFuncSetAttribute(mma_gemm<1>, cudaFuncAttributeMaxDynamicSharedMemorySize, MMA_SMEM_BYTES);

    prep_kernel<<<1, 512>>>(ei, E, N);
    convert_init_kernel<<<(n4 + 255) / 256, 256>>>(x, eps, n4);
    scatter_kernel<<<(E + 63) / 64, 256>>>(ei, E);

    int gblocks = (N + 127) / 128;
    mma_gemm<0><<<gblocks, 512, MMA_SMEM_BYTES>>>(W1, b1, nullptr, nullptr, nullptr, invM, N);
    mma_gemm<1><<<gblocks, 512, MMA_SMEM_BYTES>>>(W2, b2, g1, be1, out, invM, N);
    bn_relu_out_kernel<<<888, 256>>>(out, g2, be2, invM, n4);
}

// round 16
// speedup vs baseline: 1.3270x; 1.0021x over previous
#include <cuda_runtime.h>
#include <cuda_fp16.h>
#include <cstdint>

#define NNODES 50000
#define DFEAT 128

// ---- scratch (device globals: no allocation allowed) ----
__device__ __align__(256) float  g_H[NNODES * DFEAT];   // h = (1+eps)*x + agg
__device__ __align__(256) float  g_Z1[NNODES * DFEAT];  // pre-BN output of linear1
__device__ __align__(256) __half g_Xh[NNODES * DFEAT];  // fp16 mirror of x (gather source)
__device__ __align__(256) double g_stats[512];          // sum1,sq1,sum2,sq2 (128 each)
__device__ int g_is64;                                  // edge_index dtype flag

__device__ __forceinline__ uint32_t smem_u32(const void* p) {
    uint32_t a;
    asm("{ .reg .u64 t; cvta.to.shared.u64 t, %1; cvt.u32.u64 %0, t; }" : "=r"(a) : "l"(p));
    return a;
}

// ============================ small kernels ============================

// zero stats + probe edge dtype. One block, 512 threads.
__global__ void prep_kernel(const void* eiv, int E, int N) {
    int t = threadIdx.x;
    g_stats[t] = 0.0;
    __shared__ int bad;
    if (t == 0) bad = 0;
    __syncthreads();
    const long long* p = (const long long*)eiv;
    int n = E < 1024 ? E : 1024;
    for (int i = t; i < n; i += blockDim.x) {
        long long v = p[i];
        if (v < 0 || v >= (long long)N) atomicOr(&bad, 1);
    }
    __syncthreads();
    if (t == 0) g_is64 = bad ? 0 : 1;
}

// fused: g_H = (1+eps)*x (fp32)  AND  g_Xh = fp16(x)
__global__ void convert_init_kernel(const float* __restrict__ x,
                                    const float* __restrict__ eps, int n4) {
    int idx = blockIdx.x * blockDim.x + threadIdx.x;
    if (idx >= n4) return;
    float c = 1.0f + *eps;
    float4 v = ((const float4*)x)[idx];
    __half2 h0 = __floats2half2_rn(v.x, v.y);
    __half2 h1 = __floats2half2_rn(v.z, v.w);
    ((uint2*)g_Xh)[idx] = make_uint2(*(uint32_t*)&h0, *(uint32_t*)&h1);
    ((float4*)g_H)[idx] = make_float4(v.x * c, v.y * c, v.z * c, v.w * c);
}

// edge scatter-add: 8 edges per warp (MLP=8); gather fp16 (half the read
// bytes), accumulate with fp32 vector L2 reductions (precision preserved).
__global__ void __launch_bounds__(256) scatter_kernel(const void* __restrict__ eiv, int E) {
    int lane = threadIdx.x & 31;
    int warp = (blockIdx.x * blockDim.x + threadIdx.x) >> 5;
    int e0 = warp * 8;
    if (e0 >= E) return;
    int is64 = g_is64;

    if (e0 + 8 <= E) {
        long long s[8], d[8];
        if (is64) {
            const long long* ei = (const long long*)eiv;
#pragma unroll
            for (int k = 0; k < 8; k++) { s[k] = __ldg(&ei[e0 + k]); d[k] = __ldg(&ei[E + e0 + k]); }
        } else {
            const int* ei = (const int*)eiv;
#pragma unroll
            for (int k = 0; k < 8; k++) { s[k] = __ldg(&ei[e0 + k]); d[k] = __ldg(&ei[E + e0 + k]); }
        }
        uint2 hv[8];
#pragma unroll
        for (int k = 0; k < 8; k++)
            hv[k] = __ldg(((const uint2*)(g_Xh + s[k] * 128)) + lane);
#pragma unroll
        for (int k = 0; k < 8; k++) {
            float2 f0 = __half22float2(*(__half2*)&hv[k].x);
            float2 f1 = __half22float2(*(__half2*)&hv[k].y);
            float* dp = g_H + d[k] * 128 + (lane << 2);
            asm volatile("red.global.add.v4.f32 [%0], {%1,%2,%3,%4};"
                         :: "l"(dp), "f"(f0.x), "f"(f0.y), "f"(f1.x), "f"(f1.y) : "memory");
        }
    } else {
        for (int e = e0; e < E; e++) {
            long long s, d;
            if (is64) {
                const long long* ei = (const long long*)eiv;
                s = __ldg(&ei[e]); d = __ldg(&ei[E + e]);
            } else {
                const int* ei = (const int*)eiv;
                s = __ldg(&ei[e]); d = __ldg(&ei[E + e]);
            }
            uint2 hv = __ldg(((const uint2*)(g_Xh + s * 128)) + lane);
            float2 f0 = __half22float2(*(__half2*)&hv.x);
            float2 f1 = __half22float2(*(__half2*)&hv.y);
            float* dp = g_H + d * 128 + (lane << 2);
            asm volatile("red.global.add.v4.f32 [%0], {%1,%2,%3,%4};"
                         :: "l"(dp), "f"(f0.x), "f"(f0.y), "f"(f1.x), "f"(f1.y) : "memory");
        }
    }
}

// ============================ fp16 mma.sync GEMM ============================
// Z[m][n] = bias[n] + sum_k f(A[m][k]) * W[n][k], fp16 inputs / fp32 accum.
// MODE 0: A=g_H,  f=identity,                          Z=g_Z1
// MODE 1: A=g_Z1, f=relu(bn1(.)), bn1 finalized inline, Z=Zout
// Block: 128x128 tile, K=128 in smem as packed half2 (row stride 68 uint32).
// 512 threads = 16 warps in 4(m) x 4(n); warp tile 32x32; mma.m16n8k16.f16.
// Fragment loads via ldmatrix.x4 (4 LDSM replace 16 LDS per k-step); rows
// stride 68 words -> ldmatrix rows cover all 32 banks once (conflict-free).
// Register double-buffered fragments; column sum/sumsq fused in epilogue.
#define MMA_SMEM_U32 (640 + 2 * 128 * 68)
#define MMA_SMEM_BYTES (MMA_SMEM_U32 * 4)

__device__ __forceinline__ void mma_f16_16n8k16(float c[4], const uint32_t a[4],
                                                uint32_t b0, uint32_t b1) {
    asm volatile(
        "mma.sync.aligned.m16n8k16.row.col.f32.f16.f16.f32 "
        "{%0,%1,%2,%3}, {%4,%5,%6,%7}, {%8,%9}, {%0,%1,%2,%3};"
        : "+f"(c[0]), "+f"(c[1]), "+f"(c[2]), "+f"(c[3])
        : "r"(a[0]), "r"(a[1]), "r"(a[2]), "r"(a[3]), "r"(b0), "r"(b1));
}

#define LDSM_X4(r0, r1, r2, r3, addr) \
    asm volatile("ldmatrix.sync.aligned.m8n8.x4.shared.b16 {%0,%1,%2,%3}, [%4];" \
                 : "=r"(r0), "=r"(r1), "=r"(r2), "=r"(r3) : "r"(addr))

__device__ __forceinline__ uint32_t pack_h2(float x, float y) {
    __half2 h = __floats2half2_rn(x, y);
    return *(uint32_t*)&h;
}

template <int MODE>
__global__ void __launch_bounds__(512, 2) mma_gemm(const float* __restrict__ Wmat,
                                                   const float* __restrict__ bias,
                                                   const float* __restrict__ gamma,
                                                   const float* __restrict__ beta,
                                                   float* __restrict__ Zout,
                                                   double invM, int M) {
    extern __shared__ float sm[];
    float* s_bias  = sm;
    float* s_scale = sm + 128;
    float* s_shift = sm + 256;
    float* s_sum   = sm + 384;
    float* s_sq    = sm + 512;
    uint32_t* As16 = (uint32_t*)(sm + 640);        // [128][68] packed half2
    uint32_t* Bs16 = As16 + 128 * 68;              // [128][68] packed half2, [n][k]

    const float* A = MODE ? g_Z1 : g_H;
    float* Z       = MODE ? Zout : g_Z1;

    int tid = threadIdx.x;
    int m0 = blockIdx.x * 128;

    if (tid < 128) {
        s_bias[tid] = bias[tid];
        s_sum[tid] = 0.f;
        s_sq[tid]  = 0.f;
        if (MODE) {
            // inline BN1 finalize from g_stats (mul-only, invM precomputed on host)
            double mean = g_stats[tid] * invM;
            double var  = g_stats[128 + tid] * invM - mean * mean;
            float sc = gamma[tid] * rsqrtf((float)var + 1e-5f);
            s_scale[tid] = sc;
            s_shift[tid] = beta[tid] - (float)mean * sc;
        }
    }
    __syncthreads();

    // load B (=W, [n][k] natural layout), fp16-packed (4096 float4)
#pragma unroll
    for (int i = 0; i < 8; i++) {
        int idx = i * 512 + tid;
        int n = idx >> 5, k4 = idx & 31;
        float4 v = __ldg(((const float4*)Wmat) + idx);
        *(uint2*)(Bs16 + n * 68 + k4 * 2) =
            make_uint2(pack_h2(v.x, v.y), pack_h2(v.z, v.w));
    }
    // load A tile (fused bn1+relu in MODE 1), fp16-packed
#pragma unroll
    for (int i = 0; i < 8; i++) {
        int idx = i * 512 + tid;
        int m = idx >> 5, k4 = idx & 31;
        int gm = m0 + m;
        float4 v = make_float4(0.f, 0.f, 0.f, 0.f);
        if (gm < M) v = __ldg(((const float4*)A) + (size_t)gm * 32 + k4);
        if (MODE) {
            int k = k4 * 4;
            v.x = fmaxf(fmaf(v.x, s_scale[k + 0], s_shift[k + 0]), 0.f);
            v.y = fmaxf(fmaf(v.y, s_scale[k + 1], s_shift[k + 1]), 0.f);
            v.z = fmaxf(fmaf(v.z, s_scale[k + 2], s_shift[k + 2]), 0.f);
            v.w = fmaxf(fmaf(v.w, s_scale[k + 3], s_shift[k + 3]), 0.f);
        }
        *(uint2*)(As16 + m * 68 + k4 * 2) =
            make_uint2(pack_h2(v.x, v.y), pack_h2(v.z, v.w));
    }
    __syncthreads();

    int lane = tid & 31;
    int wid  = tid >> 5;                   // 0..15
    int g = lane >> 2, t = lane & 3;
    int wm = wid >> 2;                     // 0..3
    int wn = wid & 3;                      // 0..3
    int arow = wm * 32;                    // warp's A row base (in tile)
    int bcol = wn * 32;                    // warp's B col base (in tile)

    // ldmatrix per-warp address bases (byte addresses in shared space).
    // A x4 tiles: t0=(rows arow..+7, k lo) t1=(arow+8..15, k lo)
    //             t2=(arow..+7, k hi)     t3=(arow+8..15, k hi)
    //   lanes 0-15 -> rows arow+ (lane&15), j+0 ; lanes 16-31 -> same rows, j+4
    // B x4 tiles (pair p covers nt=2p, 2p+1):
    //   sub = lane>>3: 0:(nt=2p, k lo) 1:(nt=2p, k hi) 2:(nt=2p+1, k lo) 3:(nt=2p+1, k hi)
    uint32_t asBase = smem_u32(As16);
    uint32_t bsBase = smem_u32(Bs16);
    int lr  = lane & 15;
    int ajx = (lane >> 4) * 4;
    uint32_t aAddr[2];
#pragma unroll
    for (int mt = 0; mt < 2; mt++)
        aAddr[mt] = asBase + (((arow + mt * 16 + lr) * 68) + ajx) * 4;
    int sub = lane >> 3;
    int bn  = (sub >> 1) * 8 + (lane & 7);
    int bjx = (sub & 1) * 4;
    uint32_t bAddr[2];
#pragma unroll
    for (int p = 0; p < 2; p++)
        bAddr[p] = bsBase + (((bcol + p * 16 + bn) * 68) + bjx) * 4;

    float acc[2][4][4];
#pragma unroll
    for (int mt = 0; mt < 2; mt++)
#pragma unroll
        for (int nt = 0; nt < 4; nt++)
#pragma unroll
            for (int q = 0; q < 4; q++) acc[mt][nt][q] = 0.f;

    // double-buffered fragments (uint32 = half2)
    uint32_t a[2][2][4];
    uint32_t b[2][4][2];

#define LOAD_FRAG(ks, buf)                                                     \
    do {                                                                       \
        uint32_t _off = (uint32_t)(ks) * 32;                                   \
        LDSM_X4(a[buf][0][0], a[buf][0][1], a[buf][0][2], a[buf][0][3],        \
                aAddr[0] + _off);                                              \
        LDSM_X4(a[buf][1][0], a[buf][1][1], a[buf][1][2], a[buf][1][3],        \
                aAddr[1] + _off);                                              \
        LDSM_X4(b[buf][0][0], b[buf][0][1], b[buf][1][0], b[buf][1][1],        \
                bAddr[0] + _off);                                              \
        LDSM_X4(b[buf][2][0], b[buf][2][1], b[buf][3][0], b[buf][3][1],        \
                bAddr[1] + _off);                                              \
    } while (0)

    LOAD_FRAG(0, 0);
#pragma unroll
    for (int ks = 0; ks < 8; ks++) {
        int cur = ks & 1;
        if (ks < 7) LOAD_FRAG(ks + 1, cur ^ 1);
#pragma unroll
        for (int nt = 0; nt < 4; nt++) {
            mma_f16_16n8k16(acc[0][nt], a[cur][0], b[cur][nt][0], b[cur][nt][1]);
            mma_f16_16n8k16(acc[1][nt], a[cur][1], b[cur][nt][0], b[cur][nt][1]);
        }
    }
#undef LOAD_FRAG

    // epilogue: bias add, store float2 pairs, fused column stats
#pragma unroll
    for (int nt = 0; nt < 4; nt++) {
        int col = bcol + nt * 8 + 2 * t;
        float bi0 = s_bias[col], bi1 = s_bias[col + 1];
        float cs0 = 0.f, cq0 = 0.f, cs1 = 0.f, cq1 = 0.f;
#pragma unroll
        for (int mt = 0; mt < 2; mt++) {
#pragma unroll
            for (int rr = 0; rr < 2; rr++) {
                int gm = m0 + arow + mt * 16 + g + rr * 8;
                if (gm < M) {
                    float o0 = acc[mt][nt][rr * 2 + 0] + bi0;
                    float o1 = acc[mt][nt][rr * 2 + 1] + bi1;
                    *(float2*)(Z + (size_t)gm * 128 + col) = make_float2(o0, o1);
                    cs0 += o0; cq0 += o0 * o0;
                    cs1 += o1; cq1 += o1 * o1;
                }
            }
        }
        atomicAdd(&s_sum[col], cs0);     atomicAdd(&s_sq[col], cq0);
        atomicAdd(&s_sum[col + 1], cs1); atomicAdd(&s_sq[col + 1], cq1);
    }
    __syncthreads();
    if (tid < 128) {
        double* sum = g_stats + (MODE ? 256 : 0);
        double* sq  = g_stats + (MODE ? 384 : 128);
        atomicAdd(&sum[tid], (double)s_sum[tid]);
        atomicAdd(&sq[tid],  (double)s_sq[tid]);
    }
}

// ---- final: out = relu(bn2(out)) in place; BN2 finalize inlined (mul-only),
//      grid-stride so only ~888 blocks recompute it ----
__global__ void bn_relu_out_kernel(float* __restrict__ out,
                                   const float* __restrict__ gamma,
                                   const float* __restrict__ beta,
                                   double invM, int n4) {
    __shared__ float sc[128], sh[128];
    int t = threadIdx.x;
    if (t < 128) {
        double mean = g_stats[256 + t] * invM;
        double var  = g_stats[384 + t] * invM - mean * mean;
        float s = gamma[t] * rsqrtf((float)var + 1e-5f);
        sc[t] = s;
        sh[t] = beta[t] - (float)mean * s;
    }
    __syncthreads();
    for (int idx = blockIdx.x * blockDim.x + t; idx < n4; idx += gridDim.x * blockDim.x) {
        float4 v = ((float4*)out)[idx];
        int k = (idx & 31) * 4;
        v.x = fmaxf(fmaf(v.x, sc[k + 0], sh[k + 0]), 0.f);
        v.y = fmaxf(fmaf(v.y, sc[k + 1], sh[k + 1]), 0.f);
        v.z = fmaxf(fmaf(v.z, sc[k + 2], sh[k + 2]), 0.f);
        v.w = fmaxf(fmaf(v.w, sc[k + 3], sh[k + 3]), 0.f);
        ((float4*)out)[idx] = v;
    }
}

extern "C" void kernel_launch(void* const* d_in, const int* in_sizes, int n_in,
                              void* d_out, int out_size) {
    const float* x   = (const float*)d_in[0];
    const void*  ei  = d_in[1];
    // d_in[2] = batch (unused; single graph, BN over all nodes)
    const float* eps = (const float*)d_in[3];
    const float* W1  = (const float*)d_in[4];
    const float* b1  = (const float*)d_in[5];
    const float* g1  = (const float*)d_in[6];
    const float* be1 = (const float*)d_in[7];
    const float* W2  = (const float*)d_in[8];
    const float* b2  = (const float*)d_in[9];
    const float* g2  = (const float*)d_in[10];
    const float* be2 = (const float*)d_in[11];
    float* out = (float*)d_out;

    int N = in_sizes[0] / 128;
    int E = in_sizes[1] / 2;
    int n4 = N * 32;
    double invM = 1.0 / (double)N;

    cudaFuncSetAttribute(mma_gemm<0>, cudaFuncAttributeMaxDynamicSharedMemorySize, MMA_SMEM_BYTES);
    cudaFuncSetAttribute(mma_gemm<1>, cudaFuncAttributeMaxDynamicSharedMemorySize, MMA_SMEM_BYTES);

    prep_kernel<<<1, 512>>>(ei, E, N);
    convert_init_kernel<<<(n4 + 255) / 256, 256>>>(x, eps, n4);
    scatter_kernel<<<(E + 63) / 64, 256>>>(ei, E);

    int gblocks = (N + 127) / 128;
    mma_gemm<0><<<gblocks, 512, MMA_SMEM_BYTES>>>(W1, b1, nullptr, nullptr, nullptr, invM, N);
    mma_gemm<1><<<gblocks, 512, MMA_SMEM_BYTES>>>(W2, b2, g1, be1, out, invM, N);
    bn_relu_out_kernel<<<888, 256>>>(out, g2, be2, invM, n4);
}

// round 17
// speedup vs baseline: 1.3408x; 1.0104x over previous
#include <cuda_runtime.h>
#include <cuda_fp16.h>
#include <cstdint>

#define NNODES 50000
#define DFEAT 128

// ---- scratch (device globals: no allocation allowed) ----
__device__ __align__(256) float  g_H[NNODES * DFEAT];   // h = (1+eps)*x + agg
__device__ __align__(256) __half g_Z1h[NNODES * DFEAT]; // fp16 pre-BN output of linear1
__device__ __align__(256) __half g_Xh[NNODES * DFEAT];  // fp16 mirror of x (gather source)
__device__ __align__(256) __half g_W1h[DFEAT * DFEAT];  // fp16 W1 [n][k]
__device__ __align__(256) __half g_W2h[DFEAT * DFEAT];  // fp16 W2 [n][k]
__device__ __align__(256) double g_stats[512];          // sum1,sq1,sum2,sq2 (128 each)
__device__ int g_is64;                                  // edge_index dtype flag

__device__ __forceinline__ uint32_t smem_u32(const void* p) {
    uint32_t a;
    asm("{ .reg .u64 t; cvta.to.shared.u64 t, %1; cvt.u32.u64 %0, t; }" : "=r"(a) : "l"(p));
    return a;
}
__device__ __forceinline__ uint32_t pack_h2(float x, float y) {
    __half2 h = __floats2half2_rn(x, y);
    return *(uint32_t*)&h;
}

// ============================ small kernels ============================

// block 0: zero stats + probe edge dtype; blocks 1..16: convert W1/W2 to fp16.
__global__ void prep_kernel(const void* eiv, int E, int N,
                            const float* __restrict__ W1, const float* __restrict__ W2) {
    int tid = threadIdx.x;
    if (blockIdx.x == 0) {
        g_stats[tid] = 0.0;
        __shared__ int bad;
        if (tid == 0) bad = 0;
        __syncthreads();
        const long long* p = (const long long*)eiv;
        int n = E < 1024 ? E : 1024;
        for (int i = tid; i < n; i += blockDim.x) {
            long long v = p[i];
            if (v < 0 || v >= (long long)N) atomicOr(&bad, 1);
        }
        __syncthreads();
        if (tid == 0) g_is64 = bad ? 0 : 1;
    } else {
        int idx = (blockIdx.x - 1) * 512 + tid;   // 0..8191 float4 across W1,W2
        const float* W = idx < 4096 ? W1 : W2;
        __half* Wh     = idx < 4096 ? g_W1h : g_W2h;
        int j = idx & 4095;
        float4 v = __ldg(((const float4*)W) + j);
        ((uint2*)Wh)[j] = make_uint2(pack_h2(v.x, v.y), pack_h2(v.z, v.w));
    }
}

// fused: g_H = (1+eps)*x (fp32)  AND  g_Xh = fp16(x)
__global__ void convert_init_kernel(const float* __restrict__ x,
                                    const float* __restrict__ eps, int n4) {
    int idx = blockIdx.x * blockDim.x + threadIdx.x;
    if (idx >= n4) return;
    float c = 1.0f + *eps;
    float4 v = ((const float4*)x)[idx];
    ((uint2*)g_Xh)[idx] = make_uint2(pack_h2(v.x, v.y), pack_h2(v.z, v.w));
    ((float4*)g_H)[idx] = make_float4(v.x * c, v.y * c, v.z * c, v.w * c);
}

// edge scatter-add: 8 edges per warp (MLP=8); gather fp16, fp32 L2 reductions.
__global__ void __launch_bounds__(256) scatter_kernel(const void* __restrict__ eiv, int E) {
    int lane = threadIdx.x & 31;
    int warp = (blockIdx.x * blockDim.x + threadIdx.x) >> 5;
    int e0 = warp * 8;
    if (e0 >= E) return;
    int is64 = g_is64;

    if (e0 + 8 <= E) {
        long long s[8], d[8];
        if (is64) {
            const long long* ei = (const long long*)eiv;
#pragma unroll
            for (int k = 0; k < 8; k++) { s[k] = __ldg(&ei[e0 + k]); d[k] = __ldg(&ei[E + e0 + k]); }
        } else {
            const int* ei = (const int*)eiv;
#pragma unroll
            for (int k = 0; k < 8; k++) { s[k] = __ldg(&ei[e0 + k]); d[k] = __ldg(&ei[E + e0 + k]); }
        }
        uint2 hv[8];
#pragma unroll
        for (int k = 0; k < 8; k++)
            hv[k] = __ldg(((const uint2*)(g_Xh + s[k] * 128)) + lane);
#pragma unroll
        for (int k = 0; k < 8; k++) {
            float2 f0 = __half22float2(*(__half2*)&hv[k].x);
            float2 f1 = __half22float2(*(__half2*)&hv[k].y);
            float* dp = g_H + d[k] * 128 + (lane << 2);
            asm volatile("red.global.add.v4.f32 [%0], {%1,%2,%3,%4};"
                         :: "l"(dp), "f"(f0.x), "f"(f0.y), "f"(f1.x), "f"(f1.y) : "memory");
        }
    } else {
        for (int e = e0; e < E; e++) {
            long long s, d;
            if (is64) {
                const long long* ei = (const long long*)eiv;
                s = __ldg(&ei[e]); d = __ldg(&ei[E + e]);
            } else {
                const int* ei = (const int*)eiv;
                s = __ldg(&ei[e]); d = __ldg(&ei[E + e]);
            }
            uint2 hv = __ldg(((const uint2*)(g_Xh + s * 128)) + lane);
            float2 f0 = __half22float2(*(__half2*)&hv.x);
            float2 f1 = __half22float2(*(__half2*)&hv.y);
            float* dp = g_H + d * 128 + (lane << 2);
            asm volatile("red.global.add.v4.f32 [%0], {%1,%2,%3,%4};"
                         :: "l"(dp), "f"(f0.x), "f"(f0.y), "f"(f1.x), "f"(f1.y) : "memory");
        }
    }
}

// ============================ fp16 mma.sync GEMM ============================
// Z[m][n] = bias[n] + sum_k f(A[m][k]) * W[n][k], fp16 inputs / fp32 accum.
// MODE 0: A=g_H (fp32), f=identity,                  Z -> g_Z1h (fp16)
// MODE 1: A=g_Z1h (fp16), f=relu(bn1(.)) inline,     Z -> Zout (fp32)
// W pre-converted fp16 (g_W1h/g_W2h): load phase is a pure 32KB uint4 copy.
// Block: 128x128 tile, K=128 in smem packed half2 (row stride 68 u32).
// 512 threads = 16 warps 4(m)x4(n); warp tile 32x32; mma.m16n8k16 + ldmatrix.
// Column sum/sumsq (exact fp32) fused in epilogue.
#define MMA_SMEM_U32 (640 + 2 * 128 * 68)
#define MMA_SMEM_BYTES (MMA_SMEM_U32 * 4)

__device__ __forceinline__ void mma_f16_16n8k16(float c[4], const uint32_t a[4],
                                                uint32_t b0, uint32_t b1) {
    asm volatile(
        "mma.sync.aligned.m16n8k16.row.col.f32.f16.f16.f32 "
        "{%0,%1,%2,%3}, {%4,%5,%6,%7}, {%8,%9}, {%0,%1,%2,%3};"
        : "+f"(c[0]), "+f"(c[1]), "+f"(c[2]), "+f"(c[3])
        : "r"(a[0]), "r"(a[1]), "r"(a[2]), "r"(a[3]), "r"(b0), "r"(b1));
}

#define LDSM_X4(r0, r1, r2, r3, addr) \
    asm volatile("ldmatrix.sync.aligned.m8n8.x4.shared.b16 {%0,%1,%2,%3}, [%4];" \
                 : "=r"(r0), "=r"(r1), "=r"(r2), "=r"(r3) : "r"(addr))

template <int MODE>
__global__ void __launch_bounds__(512, 2) mma_gemm(const float* __restrict__ bias,
                                                   const float* __restrict__ gamma,
                                                   const float* __restrict__ beta,
                                                   float* __restrict__ Zout,
                                                   double invM, int M) {
    extern __shared__ float sm[];
    float* s_bias  = sm;
    float* s_scale = sm + 128;
    float* s_shift = sm + 256;
    float* s_sum   = sm + 384;
    float* s_sq    = sm + 512;
    uint32_t* As16 = (uint32_t*)(sm + 640);        // [128][68] packed half2
    uint32_t* Bs16 = As16 + 128 * 68;              // [128][68] packed half2, [n][k]

    const __half* Wh = MODE ? g_W2h : g_W1h;

    int tid = threadIdx.x;
    int m0 = blockIdx.x * 128;

    if (tid < 128) {
        s_bias[tid] = bias[tid];
        s_sum[tid] = 0.f;
        s_sq[tid]  = 0.f;
        if (MODE) {
            double mean = g_stats[tid] * invM;
            double var  = g_stats[128 + tid] * invM - mean * mean;
            float sc = gamma[tid] * rsqrtf((float)var + 1e-5f);
            s_scale[tid] = sc;
            s_shift[tid] = beta[tid] - (float)mean * sc;
        }
    }
    __syncthreads();

    // load B (=W fp16, [n][k]): pure uint4 copy, 2048 x 16B
#pragma unroll
    for (int i = 0; i < 4; i++) {
        int idx = i * 512 + tid;
        int n = idx >> 4, k16 = idx & 15;
        uint4 v = __ldg(((const uint4*)Wh) + idx);
        *(uint4*)(Bs16 + n * 68 + k16 * 4) = v;
    }
    if (MODE == 0) {
        // A = g_H fp32 -> fp16 pack
#pragma unroll
        for (int i = 0; i < 8; i++) {
            int idx = i * 512 + tid;
            int m = idx >> 5, k4 = idx & 31;
            int gm = m0 + m;
            float4 v = make_float4(0.f, 0.f, 0.f, 0.f);
            if (gm < M) v = __ldg(((const float4*)g_H) + (size_t)gm * 32 + k4);
            *(uint2*)(As16 + m * 68 + k4 * 2) =
                make_uint2(pack_h2(v.x, v.y), pack_h2(v.z, v.w));
        }
    } else {
        // A = relu(bn1(g_Z1h)) : fp16 in, fp32 BN, fp16 out
#pragma unroll
        for (int i = 0; i < 4; i++) {
            int idx = i * 512 + tid;
            int m = idx >> 4, k16 = idx & 15;
            int gm = m0 + m;
            uint4 hv = make_uint4(0u, 0u, 0u, 0u);
            if (gm < M) hv = __ldg(((const uint4*)g_Z1h) + (size_t)gm * 16 + k16);
            uint32_t w[4] = {hv.x, hv.y, hv.z, hv.w};
            uint32_t o[4];
#pragma unroll
            for (int j = 0; j < 4; j++) {
                int k = k16 * 8 + j * 2;
                float2 f = __half22float2(*(__half2*)&w[j]);
                f.x = fmaxf(fmaf(f.x, s_scale[k + 0], s_shift[k + 0]), 0.f);
                f.y = fmaxf(fmaf(f.y, s_scale[k + 1], s_shift[k + 1]), 0.f);
                o[j] = pack_h2(f.x, f.y);
            }
            *(uint4*)(As16 + m * 68 + k16 * 4) = make_uint4(o[0], o[1], o[2], o[3]);
        }
    }
    __syncthreads();

    int lane = tid & 31;
    int wid  = tid >> 5;                   // 0..15
    int g = lane >> 2, t = lane & 3;
    int wm = wid >> 2;                     // 0..3
    int wn = wid & 3;                      // 0..3
    int arow = wm * 32;
    int bcol = wn * 32;

    uint32_t asBase = smem_u32(As16);
    uint32_t bsBase = smem_u32(Bs16);
    int lr  = lane & 15;
    int ajx = (lane >> 4) * 4;
    uint32_t aAddr[2];
#pragma unroll
    for (int mt = 0; mt < 2; mt++)
        aAddr[mt] = asBase + (((arow + mt * 16 + lr) * 68) + ajx) * 4;
    int sub = lane >> 3;
    int bn  = (sub >> 1) * 8 + (lane & 7);
    int bjx = (sub & 1) * 4;
    uint32_t bAddr[2];
#pragma unroll
    for (int p = 0; p < 2; p++)
        bAddr[p] = bsBase + (((bcol + p * 16 + bn) * 68) + bjx) * 4;

    float acc[2][4][4];
#pragma unroll
    for (int mt = 0; mt < 2; mt++)
#pragma unroll
        for (int nt = 0; nt < 4; nt++)
#pragma unroll
            for (int q = 0; q < 4; q++) acc[mt][nt][q] = 0.f;

    uint32_t a[2][2][4];
    uint32_t b[2][4][2];

#define LOAD_FRAG(ks, buf)                                                     \
    do {                                                                       \
        uint32_t _off = (uint32_t)(ks) * 32;                                   \
        LDSM_X4(a[buf][0][0], a[buf][0][1], a[buf][0][2], a[buf][0][3],        \
                aAddr[0] + _off);                                              \
        LDSM_X4(a[buf][1][0], a[buf][1][1], a[buf][1][2], a[buf][1][3],        \
                aAddr[1] + _off);                                              \
        LDSM_X4(b[buf][0][0], b[buf][0][1], b[buf][1][0], b[buf][1][1],        \
                bAddr[0] + _off);                                              \
        LDSM_X4(b[buf][2][0], b[buf][2][1], b[buf][3][0], b[buf][3][1],        \
                bAddr[1] + _off);                                              \
    } while (0)

    LOAD_FRAG(0, 0);
#pragma unroll
    for (int ks = 0; ks < 8; ks++) {
        int cur = ks & 1;
        if (ks < 7) LOAD_FRAG(ks + 1, cur ^ 1);
#pragma unroll
        for (int nt = 0; nt < 4; nt++) {
            mma_f16_16n8k16(acc[0][nt], a[cur][0], b[cur][nt][0], b[cur][nt][1]);
            mma_f16_16n8k16(acc[1][nt], a[cur][1], b[cur][nt][0], b[cur][nt][1]);
        }
    }
#undef LOAD_FRAG

    // epilogue: bias add, stats from exact fp32, store (fp16 for MODE 0)
#pragma unroll
    for (int nt = 0; nt < 4; nt++) {
        int col = bcol + nt * 8 + 2 * t;
        float bi0 = s_bias[col], bi1 = s_bias[col + 1];
        float cs0 = 0.f, cq0 = 0.f, cs1 = 0.f, cq1 = 0.f;
#pragma unroll
        for (int mt = 0; mt < 2; mt++) {
#pragma unroll
            for (int rr = 0; rr < 2; rr++) {
                int gm = m0 + arow + mt * 16 + g + rr * 8;
                if (gm < M) {
                    float o0 = acc[mt][nt][rr * 2 + 0] + bi0;
                    float o1 = acc[mt][nt][rr * 2 + 1] + bi1;
                    if (MODE == 0) {
                        *(uint32_t*)(g_Z1h + (size_t)gm * 128 + col) = pack_h2(o0, o1);
                    } else {
                        *(float2*)(Zout + (size_t)gm * 128 + col) = make_float2(o0, o1);
                    }
                    cs0 += o0; cq0 += o0 * o0;
                    cs1 += o1; cq1 += o1 * o1;
                }
            }
        }
        atomicAdd(&s_sum[col], cs0);     atomicAdd(&s_sq[col], cq0);
        atomicAdd(&s_sum[col + 1], cs1); atomicAdd(&s_sq[col + 1], cq1);
    }
    __syncthreads();
    if (tid < 128) {
        double* sum = g_stats + (MODE ? 256 : 0);
        double* sq  = g_stats + (MODE ? 384 : 128);
        atomicAdd(&sum[tid], (double)s_sum[tid]);
        atomicAdd(&sq[tid],  (double)s_sq[tid]);
    }
}

// ---- final: out = relu(bn2(out)) in place; BN2 finalize inlined (mul-only) ----
__global__ void bn_relu_out_kernel(float* __restrict__ out,
                                   const float* __restrict__ gamma,
                                   const float* __restrict__ beta,
                                   double invM, int n4) {
    __shared__ float sc[128], sh[128];
    int t = threadIdx.x;
    if (t < 128) {
        double mean = g_stats[256 + t] * invM;
        double var  = g_stats[384 + t] * invM - mean * mean;
        float s = gamma[t] * rsqrtf((float)var + 1e-5f);
        sc[t] = s;
        sh[t] = beta[t] - (float)mean * s;
    }
    __syncthreads();
    for (int idx = blockIdx.x * blockDim.x + t; idx < n4; idx += gridDim.x * blockDim.x) {
        float4 v = ((float4*)out)[idx];
        int k = (idx & 31) * 4;
        v.x = fmaxf(fmaf(v.x, sc[k + 0], sh[k + 0]), 0.f);
        v.y = fmaxf(fmaf(v.y, sc[k + 1], sh[k + 1]), 0.f);
        v.z = fmaxf(fmaf(v.z, sc[k + 2], sh[k + 2]), 0.f);
        v.w = fmaxf(fmaf(v.w, sc[k + 3], sh[k + 3]), 0.f);
        ((float4*)out)[idx] = v;
    }
}

extern "C" void kernel_launch(void* const* d_in, const int* in_sizes, int n_in,
                              void* d_out, int out_size) {
    const float* x   = (const float*)d_in[0];
    const void*  ei  = d_in[1];
    // d_in[2] = batch (unused; single graph, BN over all nodes)
    const float* eps = (const float*)d_in[3];
    const float* W1  = (const float*)d_in[4];
    const float* b1  = (const float*)d_in[5];
    const float* g1  = (const float*)d_in[6];
    const float* be1 = (const float*)d_in[7];
    const float* W2  = (const float*)d_in[8];
    const float* b2  = (const float*)d_in[9];
    const float* g2  = (const float*)d_in[10];
    const float* be2 = (const float*)d_in[11];
    float* out = (float*)d_out;

    int N = in_sizes[0] / 128;
    int E = in_sizes[1] / 2;
    int n4 = N * 32;
    double invM = 1.0 / (double)N;

    cudaFuncSetAttribute(mma_gemm<0>, cudaFuncAttributeMaxDynamicSharedMemorySize, MMA_SMEM_BYTES);
    cudaFuncSetAttribute(mma_gemm<1>, cudaFuncAttributeMaxDynamicSharedMemorySize, MMA_SMEM_BYTES);

    prep_kernel<<<17, 512>>>(ei, E, N, W1, W2);
    convert_init_kernel<<<(n4 + 255) / 256, 256>>>(x, eps, n4);
    scatter_kernel<<<(E + 63) / 64, 256>>>(ei, E);

    int gblocks = (N + 127) / 128;
    mma_gemm<0><<<gblocks, 512, MMA_SMEM_BYTES>>>(b1, nullptr, nullptr, nullptr, invM, N);
    mma_gemm<1><<<gblocks, 512, MMA_SMEM_BYTES>>>(b2, g1, be1, out, invM, N);
    bn_relu_out_kernel<<<888, 256>>>(out, g2, be2, invM, n4);
}